// round 1
// baseline (speedup 1.0000x reference)
#include <cuda_runtime.h>
#include <math.h>

// Problem constants
#define BB   2
#define HH   16
#define SS   2048
#define DD   1024
#define DK   64
#define BHN  (BB*HH)      // 32
#define KEEP 1843         // int(2048*0.9)

// ---------------- scratch (device globals; no cudaMalloc allowed) ----------
__device__ float g_qh[(size_t)BHN * SS * DK];     // [b,h,s,d]
__device__ float g_kh[(size_t)BHN * SS * DK];
__device__ float g_vh[(size_t)BHN * SS * DK];
__device__ float g_probs[(size_t)BHN * SS * SS];  // 512 MiB softmax probs
__device__ float g_colsum[BHN * SS];
__device__ float g_mask[BHN * SS];
__device__ float g_concat[(size_t)BB * SS * DD];  // [b,s,h*64+d]

// ---------------------------------------------------------------------------
// Generic NT SGEMM: C[m,n] = alpha * sum_k A[m,k]*B[n,k]  (+bias[n])
// Both A and B are K-contiguous (lda/ldb are row strides).
// BM=BN=128, BK=8, 256 threads, 8x8 micro-tile per thread.
// mode 0: plain row-major C with ldc (+ optional per-z batch strides)
// mode 1: projection head-scatter into [b,h,s,d] layout (M=B*S, N=D)
// ---------------------------------------------------------------------------
__global__ __launch_bounds__(256, 2)
void sgemm_nt(const float* __restrict__ Ag, const float* __restrict__ Bg,
              float* __restrict__ Cg, const float* __restrict__ bias,
              int K, int lda, int ldb, int ldc,
              long long sA, long long sB, long long sC,
              float alpha, int mode)
{
    __shared__ float As[8][128];
    __shared__ float Bs[8][128];

    const float* A = Ag + (size_t)blockIdx.z * sA;
    const float* B = Bg + (size_t)blockIdx.z * sB;
    float*       C = Cg + (size_t)blockIdx.z * sC;

    const int m0 = blockIdx.y * 128;
    const int n0 = blockIdx.x * 128;
    const int tid = threadIdx.x;
    const int tx = tid & 15;        // 0..15 (n)
    const int ty = tid >> 4;        // 0..15 (m)
    const int lrow = tid >> 1;      // 0..127  (loader row)
    const int lcol = (tid & 1) * 4; // 0 or 4  (loader k-offset)

    float acc[8][8];
#pragma unroll
    for (int i = 0; i < 8; i++)
#pragma unroll
        for (int j = 0; j < 8; j++) acc[i][j] = 0.f;

    const float* Aptr = A + (size_t)(m0 + lrow) * lda + lcol;
    const float* Bptr = B + (size_t)(n0 + lrow) * ldb + lcol;

    for (int k0 = 0; k0 < K; k0 += 8) {
        float4 av = *(const float4*)(Aptr + k0);
        float4 bv = *(const float4*)(Bptr + k0);
        __syncthreads();
        As[lcol + 0][lrow] = av.x; As[lcol + 1][lrow] = av.y;
        As[lcol + 2][lrow] = av.z; As[lcol + 3][lrow] = av.w;
        Bs[lcol + 0][lrow] = bv.x; Bs[lcol + 1][lrow] = bv.y;
        Bs[lcol + 2][lrow] = bv.z; Bs[lcol + 3][lrow] = bv.w;
        __syncthreads();
#pragma unroll
        for (int kk = 0; kk < 8; kk++) {
            float a[8], b[8];
            *(float4*)(a)     = *(const float4*)&As[kk][ty * 8];
            *(float4*)(a + 4) = *(const float4*)&As[kk][ty * 8 + 4];
            *(float4*)(b)     = *(const float4*)&Bs[kk][tx * 8];
            *(float4*)(b + 4) = *(const float4*)&Bs[kk][tx * 8 + 4];
#pragma unroll
            for (int i = 0; i < 8; i++)
#pragma unroll
                for (int j = 0; j < 8; j++) acc[i][j] += a[i] * b[j];
        }
    }

    if (mode == 0) {
#pragma unroll
        for (int i = 0; i < 8; i++) {
            int m = m0 + ty * 8 + i;
            float out[8];
#pragma unroll
            for (int j = 0; j < 8; j++) {
                int n = n0 + tx * 8 + j;
                out[j] = acc[i][j] * alpha + (bias ? bias[n] : 0.f);
            }
            float* crow = C + (size_t)m * ldc + n0 + tx * 8;
            *(float4*)(crow)     = *(float4*)(out);
            *(float4*)(crow + 4) = *(float4*)(out + 4);
        }
    } else {
        // head-scatter: m -> (b,s), n -> (h,d); write [((b*H+h)*S+s)*DK+d]
#pragma unroll
        for (int i = 0; i < 8; i++) {
            int m = m0 + ty * 8 + i;
            int b = m >> 11;            // /2048
            int s = m & (SS - 1);
#pragma unroll
            for (int j = 0; j < 8; j++) {
                int n = n0 + tx * 8 + j;
                int h = n >> 6;
                int d = n & 63;
                C[(((size_t)(b * HH + h)) * SS + s) * DK + d] =
                    acc[i][j] * alpha + (bias ? bias[n] : 0.f);
            }
        }
    }
}

// ---------------------------------------------------------------------------
// Row softmax over the last axis (S=2048), in place. One block per (q, bh).
// ---------------------------------------------------------------------------
__global__ void softmax_kernel(float* __restrict__ probs)
{
    __shared__ float red[256];
    const int q = blockIdx.x;
    const int bh = blockIdx.y;
    const int tid = threadIdx.x;
    float* row = probs + ((size_t)bh * SS + q) * SS;

    float x[8];
    float m = -1e30f;
#pragma unroll
    for (int i = 0; i < 8; i++) {
        x[i] = row[tid + i * 256];
        m = fmaxf(m, x[i]);
    }
    red[tid] = m;
    __syncthreads();
    for (int s = 128; s > 0; s >>= 1) {
        if (tid < s) red[tid] = fmaxf(red[tid], red[tid + s]);
        __syncthreads();
    }
    m = red[0];
    __syncthreads();

    float sum = 0.f;
#pragma unroll
    for (int i = 0; i < 8; i++) {
        x[i] = __expf(x[i] - m);
        sum += x[i];
    }
    red[tid] = sum;
    __syncthreads();
    for (int s = 128; s > 0; s >>= 1) {
        if (tid < s) red[tid] += red[tid + s];
        __syncthreads();
    }
    float inv = 1.0f / red[0];
#pragma unroll
    for (int i = 0; i < 8; i++) row[tid + i * 256] = x[i] * inv;
}

// ---------------------------------------------------------------------------
// Column sums of probs over the query axis (deterministic, no atomics).
// grid (S/256, BH); thread k sums P[q][k] over q.
// ---------------------------------------------------------------------------
__global__ void colsum_kernel(const float* __restrict__ probs,
                              float* __restrict__ colsum)
{
    const int k = blockIdx.x * 256 + threadIdx.x;
    const int bh = blockIdx.y;
    const float* P = probs + (size_t)bh * SS * SS + k;
    float s = 0.f;
#pragma unroll 8
    for (int q = 0; q < SS; q++) s += P[(size_t)q * SS];
    colsum[bh * SS + k] = s;
}

// ---------------------------------------------------------------------------
// Top-k mask: bitonic-sort the 2048 column sums (ascending), take the
// (2048-KEEP)-th smallest as threshold, mask = colsum >= thr.
// One block of 1024 threads per (b,h).
// ---------------------------------------------------------------------------
__global__ void topk_mask_kernel(const float* __restrict__ colsum,
                                 float* __restrict__ mask)
{
    __shared__ float s[SS];
    const int bh = blockIdx.x;
    const int tid = threadIdx.x; // 1024
    const float* cs = colsum + bh * SS;
    s[tid] = cs[tid];
    s[tid + 1024] = cs[tid + 1024];
    __syncthreads();

    for (int ksz = 2; ksz <= SS; ksz <<= 1) {
        for (int j = ksz >> 1; j > 0; j >>= 1) {
            for (int i = tid; i < SS; i += 1024) {
                int p = i ^ j;
                if (p > i) {
                    bool up = ((i & ksz) == 0);
                    float a = s[i], b = s[p];
                    if ((a > b) == up) { s[i] = b; s[p] = a; }
                }
            }
            __syncthreads();
        }
    }
    float thr = s[SS - KEEP]; // ascending-sorted; exactly KEEP values are >= thr
    mask[bh * SS + tid]        = (cs[tid]        >= thr) ? 1.f : 0.f;
    mask[bh * SS + tid + 1024] = (cs[tid + 1024] >= thr) ? 1.f : 0.f;
}

// ---------------------------------------------------------------------------
// AV GEMM with column mask: out[q,d] = sum_k P[q,k]*mask[k]*V[k,d]
// BM=128, BN=64 (=DK), BK=16, 256 threads, 8x4 micro-tile.
// Writes directly into concat layout [b, s, h*64+d].
// ---------------------------------------------------------------------------
__global__ __launch_bounds__(256)
void av_kernel(const float* __restrict__ probs, const float* __restrict__ vh,
               const float* __restrict__ mask, float* __restrict__ concat)
{
    __shared__ float As[16][128];
    __shared__ float Bs[16][64];

    const int bh = blockIdx.z;
    const int b = bh >> 4;
    const int h = bh & 15;
    const float* P  = probs + (size_t)bh * SS * SS;
    const float* V  = vh    + (size_t)bh * SS * DK;
    const float* Mk = mask  + bh * SS;

    const int m0 = blockIdx.y * 128;
    const int tid = threadIdx.x;
    const int tx = tid & 15;   // n groups of 4
    const int ty = tid >> 4;   // m groups of 8

    const int arow = tid >> 1;
    const int ac0  = (tid & 1) * 4;
    const int brow = ty;        // 0..15
    const int bcol = tx * 4;    // 0..60

    float acc[8][4];
#pragma unroll
    for (int i = 0; i < 8; i++)
#pragma unroll
        for (int j = 0; j < 4; j++) acc[i][j] = 0.f;

    for (int k0 = 0; k0 < SS; k0 += 16) {
        const float* prow = P + (size_t)(m0 + arow) * SS + k0;
        float4 a0 = *(const float4*)(prow + ac0);
        float4 a1 = *(const float4*)(prow + ac0 + 8);
        float  mk = Mk[k0 + brow];
        float4 bv = *(const float4*)(V + (size_t)(k0 + brow) * DK + bcol);
        __syncthreads();
        As[ac0 + 0][arow] = a0.x; As[ac0 + 1][arow] = a0.y;
        As[ac0 + 2][arow] = a0.z; As[ac0 + 3][arow] = a0.w;
        As[ac0 + 8][arow] = a1.x; As[ac0 + 9][arow] = a1.y;
        As[ac0 +10][arow] = a1.z; As[ac0 +11][arow] = a1.w;
        Bs[brow][bcol + 0] = bv.x * mk; Bs[brow][bcol + 1] = bv.y * mk;
        Bs[brow][bcol + 2] = bv.z * mk; Bs[brow][bcol + 3] = bv.w * mk;
        __syncthreads();
#pragma unroll
        for (int kk = 0; kk < 16; kk++) {
            float a[8], bb[4];
            *(float4*)(a)     = *(const float4*)&As[kk][ty * 8];
            *(float4*)(a + 4) = *(const float4*)&As[kk][ty * 8 + 4];
            *(float4*)(bb)    = *(const float4*)&Bs[kk][bcol];
#pragma unroll
            for (int i = 0; i < 8; i++)
#pragma unroll
                for (int j = 0; j < 4; j++) acc[i][j] += a[i] * bb[j];
        }
    }

#pragma unroll
    for (int i = 0; i < 8; i++) {
        int q = m0 + ty * 8 + i;
        float* dst = concat + ((size_t)(b * SS + q)) * DD + h * DK + bcol;
        float4 o;
        o.x = acc[i][0]; o.y = acc[i][1]; o.z = acc[i][2]; o.w = acc[i][3];
        *(float4*)dst = o;
    }
}

// ---------------------------------------------------------------------------
extern "C" void kernel_launch(void* const* d_in, const int* in_sizes, int n_in,
                              void* d_out, int out_size)
{
    (void)in_sizes; (void)n_in; (void)out_size;
    const float* q  = (const float*)d_in[0];
    const float* k  = (const float*)d_in[1];
    const float* v  = (const float*)d_in[2];
    const float* Wq = (const float*)d_in[3];
    const float* bq = (const float*)d_in[4];
    const float* Wk = (const float*)d_in[5];
    const float* bk = (const float*)d_in[6];
    const float* Wv = (const float*)d_in[7];
    const float* bv = (const float*)d_in[8];
    const float* Wo = (const float*)d_in[9];
    const float* bo = (const float*)d_in[10];
    float* out = (float*)d_out;

    float *qh, *kh, *vh, *probs, *colsum, *mask, *concat;
    cudaGetSymbolAddress((void**)&qh,     g_qh);
    cudaGetSymbolAddress((void**)&kh,     g_kh);
    cudaGetSymbolAddress((void**)&vh,     g_vh);
    cudaGetSymbolAddress((void**)&probs,  g_probs);
    cudaGetSymbolAddress((void**)&colsum, g_colsum);
    cudaGetSymbolAddress((void**)&mask,   g_mask);
    cudaGetSymbolAddress((void**)&concat, g_concat);

    dim3 blk(256);

    // QKV projections: [4096,1024] @ W^T + b, head-scattered (mode 1)
    dim3 gproj(DD / 128, (BB * SS) / 128, 1);
    sgemm_nt<<<gproj, blk>>>(q, Wq, qh, bq, DD, DD, DD, 0, 0, 0, 0, 1.f, 1);
    sgemm_nt<<<gproj, blk>>>(k, Wk, kh, bk, DD, DD, DD, 0, 0, 0, 0, 1.f, 1);
    sgemm_nt<<<gproj, blk>>>(v, Wv, vh, bv, DD, DD, DD, 0, 0, 0, 0, 1.f, 1);

    // Scores: per (b,h) 2048x2048x64, alpha = 1/sqrt(64)
    dim3 gsc(SS / 128, SS / 128, BHN);
    sgemm_nt<<<gsc, blk>>>(qh, kh, probs, nullptr, DK, DK, DK, SS,
                           (long long)SS * DK, (long long)SS * DK,
                           (long long)SS * SS, 0.125f, 0);

    // Row softmax in place
    softmax_kernel<<<dim3(SS, BHN), 256>>>(probs);

    // Column sums (over queries)
    colsum_kernel<<<dim3(SS / 256, BHN), 256>>>(probs, colsum);

    // Top-k threshold -> column mask
    topk_mask_kernel<<<BHN, 1024>>>(colsum, mask);

    // Masked AV -> concat layout
    av_kernel<<<dim3(1, SS / 128, BHN), 256>>>(probs, vh, mask, concat);

    // Output projection: concat @ Wo^T + bo -> d_out
    sgemm_nt<<<gproj, blk>>>(concat, Wo, out, bo, DD, DD, DD, DD,
                             0, 0, 0, 1.f, 0);
}

// round 6
// speedup vs baseline: 1.0754x; 1.0754x over previous
#include <cuda_runtime.h>
#include <math.h>

// Problem constants
#define BB   2
#define HH   16
#define SS   2048
#define DD   1024
#define DK   64
#define BHN  (BB*HH)      // 32
#define KEEP 1843         // int(2048*0.9)

typedef unsigned int u32;

// ---------------- scratch (device globals; no cudaMalloc allowed) ----------
__device__ float g_qh[(size_t)BHN * SS * DK];     // [b,h,s,d]
__device__ float g_kh[(size_t)BHN * SS * DK];
__device__ float g_vh[(size_t)BHN * SS * DK];
__device__ float g_vtm[(size_t)BHN * DK * SS];    // masked V^T: [b,h,d,s]
__device__ float g_probs[(size_t)BHN * SS * SS];  // 512 MiB softmax probs
__device__ float g_part[(size_t)BHN * 32 * SS];   // colsum partials (8 MiB)
__device__ float g_colsum[BHN * SS];
__device__ float g_mask[BHN * SS];
__device__ float g_concat[(size_t)BB * SS * DD];  // [b,s,h*64+d]

// ============================================================================
// FFMA fp32 NT SGEMM (selection-critical path) — identical math to R1.
// C[m,n] = alpha * sum_k A[m,k]*B[n,k] (+bias[n]); A,B K-contiguous.
// BM=BN=128, BK=8, 256 threads, 8x8 micro-tile.
// mode 0: plain row-major C; mode 1: head-scatter [b,h,s,d]
// ============================================================================
__global__ __launch_bounds__(256, 2)
void sgemm_nt(const float* __restrict__ Ag, const float* __restrict__ Bg,
              float* __restrict__ Cg, const float* __restrict__ bias,
              int K, int lda, int ldb, int ldc,
              long long sA, long long sB, long long sC,
              float alpha, int mode)
{
    __shared__ float As[8][128];
    __shared__ float Bs[8][128];

    const float* A = Ag + (size_t)blockIdx.z * sA;
    const float* B = Bg + (size_t)blockIdx.z * sB;
    float*       C = Cg + (size_t)blockIdx.z * sC;

    const int m0 = blockIdx.y * 128;
    const int n0 = blockIdx.x * 128;
    const int tid = threadIdx.x;
    const int tx = tid & 15;
    const int ty = tid >> 4;
    const int lrow = tid >> 1;
    const int lcol = (tid & 1) * 4;

    float acc[8][8];
#pragma unroll
    for (int i = 0; i < 8; i++)
#pragma unroll
        for (int j = 0; j < 8; j++) acc[i][j] = 0.f;

    const float* Aptr = A + (size_t)(m0 + lrow) * lda + lcol;
    const float* Bptr = B + (size_t)(n0 + lrow) * ldb + lcol;

    for (int k0 = 0; k0 < K; k0 += 8) {
        float4 av = *(const float4*)(Aptr + k0);
        float4 bv = *(const float4*)(Bptr + k0);
        __syncthreads();
        As[lcol + 0][lrow] = av.x; As[lcol + 1][lrow] = av.y;
        As[lcol + 2][lrow] = av.z; As[lcol + 3][lrow] = av.w;
        Bs[lcol + 0][lrow] = bv.x; Bs[lcol + 1][lrow] = bv.y;
        Bs[lcol + 2][lrow] = bv.z; Bs[lcol + 3][lrow] = bv.w;
        __syncthreads();
#pragma unroll
        for (int kk = 0; kk < 8; kk++) {
            float a[8], b[8];
            *(float4*)(a)     = *(const float4*)&As[kk][ty * 8];
            *(float4*)(a + 4) = *(const float4*)&As[kk][ty * 8 + 4];
            *(float4*)(b)     = *(const float4*)&Bs[kk][tx * 8];
            *(float4*)(b + 4) = *(const float4*)&Bs[kk][tx * 8 + 4];
#pragma unroll
            for (int i = 0; i < 8; i++)
#pragma unroll
                for (int j = 0; j < 8; j++) acc[i][j] += a[i] * b[j];
        }
    }

    if (mode == 0) {
#pragma unroll
        for (int i = 0; i < 8; i++) {
            int m = m0 + ty * 8 + i;
            float out[8];
#pragma unroll
            for (int j = 0; j < 8; j++) {
                int n = n0 + tx * 8 + j;
                out[j] = acc[i][j] * alpha + (bias ? bias[n] : 0.f);
            }
            float* crow = C + (size_t)m * ldc + n0 + tx * 8;
            *(float4*)(crow)     = *(float4*)(out);
            *(float4*)(crow + 4) = *(float4*)(out + 4);
        }
    } else {
#pragma unroll
        for (int i = 0; i < 8; i++) {
            int m = m0 + ty * 8 + i;
            int b = m >> 11;
            int s = m & (SS - 1);
#pragma unroll
            for (int j = 0; j < 8; j++) {
                int n = n0 + tx * 8 + j;
                int h = n >> 6;
                int d = n & 63;
                C[(((size_t)(b * HH + h)) * SS + s) * DK + d] =
                    acc[i][j] * alpha + (bias ? bias[n] : 0.f);
            }
        }
    }
}

// ============================================================================
// 3xTF32 mma.sync NT GEMM (value path): fp32-grade via hi/lo split.
// ============================================================================
static __device__ __forceinline__ u32 f2tf(float x) {
    u32 r;
    asm("cvt.rna.tf32.f32 %0, %1;" : "=r"(r) : "f"(x));
    return r;
}
static __device__ __forceinline__ void mma_tf32(float* d, const u32* a, const u32* b) {
    asm volatile(
        "mma.sync.aligned.m16n8k8.row.col.f32.tf32.tf32.f32 "
        "{%0,%1,%2,%3}, {%4,%5,%6,%7}, {%8,%9}, {%0,%1,%2,%3};"
        : "+f"(d[0]), "+f"(d[1]), "+f"(d[2]), "+f"(d[3])
        : "r"(a[0]), "r"(a[1]), "r"(a[2]), "r"(a[3]), "r"(b[0]), "r"(b[1]));
}

template<int NT>
__global__ __launch_bounds__(256)
void mma_gemm3(const float* __restrict__ Ag, const float* __restrict__ Bg,
               float* __restrict__ Cg, const float* __restrict__ bias,
               int K, int lda, int ldb, int ldc,
               long long sA, long long sB, long long sC,
               float alpha, int mode)
{
    __shared__ u32 Ash[128][20];
    __shared__ u32 Asl[128][20];
    __shared__ u32 Bsh[NT][20];
    __shared__ u32 Bsl[NT][20];

    const int tid  = threadIdx.x;
    const int wid  = tid >> 5;
    const int lane = tid & 31;
    const int wm   = wid & 1;
    const int wn   = wid >> 1;
    const int qid  = lane >> 2;
    const int rid  = lane & 3;

    constexpr int WN  = NT / 4;
    constexpr int NFR = WN / 8;
    constexpr int A4  = 2;
    constexpr int B4  = (NT * 4) / 256;

    const float* A = Ag + (size_t)blockIdx.z * sA;
    const float* B = Bg + (size_t)blockIdx.z * sB;

    const int m0 = blockIdx.y * 128;
    const int n0 = blockIdx.x * NT;

    float acc[4][NFR][4];
#pragma unroll
    for (int i = 0; i < 4; i++)
#pragma unroll
        for (int j = 0; j < NFR; j++)
#pragma unroll
            for (int t = 0; t < 4; t++) acc[i][j][t] = 0.f;

    const int nc = K >> 4;
    for (int c = 0; c < nc; c++) {
        const int k0 = c << 4;
        float4 va[A4], vb[B4];
#pragma unroll
        for (int i = 0; i < A4; i++) {
            int idx = tid + i * 256;
            int r = idx >> 2, cc = (idx & 3) << 2;
            va[i] = *(const float4*)(A + (size_t)(m0 + r) * lda + k0 + cc);
        }
#pragma unroll
        for (int i = 0; i < B4; i++) {
            int idx = tid + i * 256;
            int r = idx >> 2, cc = (idx & 3) << 2;
            vb[i] = *(const float4*)(B + (size_t)(n0 + r) * ldb + k0 + cc);
        }
        __syncthreads();
#pragma unroll
        for (int i = 0; i < A4; i++) {
            int idx = tid + i * 256;
            int r = idx >> 2, cc = (idx & 3) << 2;
            float xs[4] = {va[i].x, va[i].y, va[i].z, va[i].w};
#pragma unroll
            for (int t = 0; t < 4; t++) {
                u32 h = f2tf(xs[t]);
                Ash[r][cc + t] = h;
                Asl[r][cc + t] = f2tf(xs[t] - __uint_as_float(h));
            }
        }
#pragma unroll
        for (int i = 0; i < B4; i++) {
            int idx = tid + i * 256;
            int r = idx >> 2, cc = (idx & 3) << 2;
            float xs[4] = {vb[i].x, vb[i].y, vb[i].z, vb[i].w};
#pragma unroll
            for (int t = 0; t < 4; t++) {
                u32 h = f2tf(xs[t]);
                Bsh[r][cc + t] = h;
                Bsl[r][cc + t] = f2tf(xs[t] - __uint_as_float(h));
            }
        }
        __syncthreads();

#pragma unroll
        for (int kk = 0; kk < 16; kk += 8) {
            u32 af[4][4], bfh[NFR][2], bfl[NFR][2];
#pragma unroll
            for (int mt = 0; mt < 4; mt++) {
                int row = wm * 64 + mt * 16 + qid;
                af[mt][0] = Ash[row    ][kk + rid];
                af[mt][1] = Ash[row + 8][kk + rid];
                af[mt][2] = Ash[row    ][kk + 4 + rid];
                af[mt][3] = Ash[row + 8][kk + 4 + rid];
            }
#pragma unroll
            for (int nt = 0; nt < NFR; nt++) {
                int col = wn * WN + nt * 8 + qid;
                bfh[nt][0] = Bsh[col][kk + rid];
                bfh[nt][1] = Bsh[col][kk + 4 + rid];
                bfl[nt][0] = Bsl[col][kk + rid];
                bfl[nt][1] = Bsl[col][kk + 4 + rid];
            }
#pragma unroll
            for (int mt = 0; mt < 4; mt++)
#pragma unroll
                for (int nt = 0; nt < NFR; nt++) {
                    mma_tf32(acc[mt][nt], af[mt], bfh[nt]);
                    mma_tf32(acc[mt][nt], af[mt], bfl[nt]);
                }
#pragma unroll
            for (int mt = 0; mt < 4; mt++) {
                int row = wm * 64 + mt * 16 + qid;
                af[mt][0] = Asl[row    ][kk + rid];
                af[mt][1] = Asl[row + 8][kk + rid];
                af[mt][2] = Asl[row    ][kk + 4 + rid];
                af[mt][3] = Asl[row + 8][kk + 4 + rid];
            }
#pragma unroll
            for (int mt = 0; mt < 4; mt++)
#pragma unroll
                for (int nt = 0; nt < NFR; nt++)
                    mma_tf32(acc[mt][nt], af[mt], bfh[nt]);
        }
    }

#pragma unroll
    for (int mt = 0; mt < 4; mt++) {
        int r0 = m0 + wm * 64 + mt * 16 + qid;
        int r1 = r0 + 8;
#pragma unroll
        for (int nt = 0; nt < NFR; nt++) {
            int cb = n0 + wn * WN + nt * 8 + rid * 2;
            float v0 = acc[mt][nt][0] * alpha;
            float v1 = acc[mt][nt][1] * alpha;
            float v2 = acc[mt][nt][2] * alpha;
            float v3 = acc[mt][nt][3] * alpha;
            if (bias) {
                float b0 = bias[cb], b1 = bias[cb + 1];
                v0 += b0; v1 += b1; v2 += b0; v3 += b1;
            }
            if (mode == 0) {
                float* base = Cg + (size_t)blockIdx.z * sC;
                *(float2*)(base + (size_t)r0 * ldc + cb) = make_float2(v0, v1);
                *(float2*)(base + (size_t)r1 * ldc + cb) = make_float2(v2, v3);
            } else if (mode == 1) {
                int h = cb >> 6, d = cb & 63;
                int b0i = r0 >> 11, s0i = r0 & (SS - 1);
                int b1i = r1 >> 11, s1i = r1 & (SS - 1);
                *(float2*)(Cg + (((size_t)(b0i * HH + h)) * SS + s0i) * DK + d) =
                    make_float2(v0, v1);
                *(float2*)(Cg + (((size_t)(b1i * HH + h)) * SS + s1i) * DK + d) =
                    make_float2(v2, v3);
            } else { // mode 3
                int z = blockIdx.z, b = z >> 4, h = z & 15;
                *(float2*)(Cg + ((size_t)b * SS + r0) * DD + h * DK + cb) =
                    make_float2(v0, v1);
                *(float2*)(Cg + ((size_t)b * SS + r1) * DD + h * DK + cb) =
                    make_float2(v2, v3);
            }
        }
    }
}

// ============================================================================
// Fused softmax + column-sum partials. One block handles 64 rows x 2048 cols.
// Deterministic: partials per (bh, rowblock) then a fixed-order reduce.
// ============================================================================
__global__ __launch_bounds__(256)
void softmax_colsum_kernel(float* __restrict__ probs, float* __restrict__ part)
{
    __shared__ float redA[8];
    __shared__ float redB[8];
    const int rb = blockIdx.x;   // 0..31
    const int bh = blockIdx.y;
    const int tid = threadIdx.x;
    const int wid = tid >> 5, lane = tid & 31;

    float cs[8];
#pragma unroll
    for (int i = 0; i < 8; i++) cs[i] = 0.f;

    for (int r = 0; r < 64; r++) {
        float* row = probs + ((size_t)bh * SS + rb * 64 + r) * SS;
        float x[8];
#pragma unroll
        for (int i = 0; i < 8; i++) x[i] = row[tid + i * 256];

        float m = x[0];
#pragma unroll
        for (int i = 1; i < 8; i++) m = fmaxf(m, x[i]);
#pragma unroll
        for (int o = 16; o > 0; o >>= 1)
            m = fmaxf(m, __shfl_xor_sync(0xFFFFFFFF, m, o));
        if (lane == 0) redA[wid] = m;
        __syncthreads();
        m = redA[0];
#pragma unroll
        for (int w = 1; w < 8; w++) m = fmaxf(m, redA[w]);

        float s = 0.f;
#pragma unroll
        for (int i = 0; i < 8; i++) {
            x[i] = __expf(x[i] - m);
            s += x[i];
        }
#pragma unroll
        for (int o = 16; o > 0; o >>= 1)
            s += __shfl_xor_sync(0xFFFFFFFF, s, o);
        if (lane == 0) redB[wid] = s;
        __syncthreads();
        s = redB[0];
#pragma unroll
        for (int w = 1; w < 8; w++) s += redB[w];
        float inv = 1.0f / s;
#pragma unroll
        for (int i = 0; i < 8; i++) {
            float p = x[i] * inv;
            row[tid + i * 256] = p;
            cs[i] += p;
        }
        __syncthreads();   // protect redA/redB reuse next row
    }
#pragma unroll
    for (int i = 0; i < 8; i++)
        part[((size_t)bh * 32 + rb) * SS + tid + i * 256] = cs[i];
}

__global__ void colsum_reduce_kernel(const float* __restrict__ part,
                                     float* __restrict__ colsum)
{
    const int k = blockIdx.x * 256 + threadIdx.x;
    const int bh = blockIdx.y;
    float s = 0.f;
#pragma unroll
    for (int rb = 0; rb < 32; rb++)
        s += part[((size_t)bh * 32 + rb) * SS + k];
    colsum[bh * SS + k] = s;
}

// ============================================================================
// Top-k mask via bitonic sort of the 2048 column sums.
// ============================================================================
__global__ void topk_mask_kernel(const float* __restrict__ colsum,
                                 float* __restrict__ mask)
{
    __shared__ float s[SS];
    const int bh = blockIdx.x;
    const int tid = threadIdx.x; // 1024
    const float* cs = colsum + bh * SS;
    s[tid] = cs[tid];
    s[tid + 1024] = cs[tid + 1024];
    __syncthreads();

    for (int ksz = 2; ksz <= SS; ksz <<= 1) {
        for (int j = ksz >> 1; j > 0; j >>= 1) {
            for (int i = tid; i < SS; i += 1024) {
                int p = i ^ j;
                if (p > i) {
                    bool up = ((i & ksz) == 0);
                    float a = s[i], b = s[p];
                    if ((a > b) == up) { s[i] = b; s[p] = a; }
                }
            }
            __syncthreads();
        }
    }
    float thr = s[SS - KEEP];
    mask[bh * SS + tid]        = (cs[tid]        >= thr) ? 1.f : 0.f;
    mask[bh * SS + tid + 1024] = (cs[tid + 1024] >= thr) ? 1.f : 0.f;
}

// ============================================================================
// Masked transpose: vtm[bh][d][s] = vh[bh][s][d] * mask[bh][s]
// ============================================================================
__global__ void vt_mask_kernel(const float* __restrict__ vh,
                               const float* __restrict__ mask,
                               float* __restrict__ vtm)
{
    __shared__ float t[32][33];
    const int bh = blockIdx.z;
    const int s0 = blockIdx.x * 32;
    const int d0 = blockIdx.y * 32;
    const int lx = threadIdx.x & 31;
    const int ly = threadIdx.x >> 5;
    for (int i = ly; i < 32; i += 8)
        t[i][lx] = vh[((size_t)bh * SS + s0 + i) * DK + d0 + lx] * mask[bh * SS + s0 + i];
    __syncthreads();
    for (int i = ly; i < 32; i += 8)
        vtm[((size_t)bh * DK + d0 + i) * SS + s0 + lx] = t[lx][i];
}

// ---------------------------------------------------------------------------
extern "C" void kernel_launch(void* const* d_in, const int* in_sizes, int n_in,
                              void* d_out, int out_size)
{
    (void)in_sizes; (void)n_in; (void)out_size;
    const float* q  = (const float*)d_in[0];
    const float* k  = (const float*)d_in[1];
    const float* v  = (const float*)d_in[2];
    const float* Wq = (const float*)d_in[3];
    const float* bq = (const float*)d_in[4];
    const float* Wk = (const float*)d_in[5];
    const float* bk = (const float*)d_in[6];
    const float* Wv = (const float*)d_in[7];
    const float* bv = (const float*)d_in[8];
    const float* Wo = (const float*)d_in[9];
    const float* bo = (const float*)d_in[10];
    float* out = (float*)d_out;

    float *qh, *kh, *vh, *vtm, *probs, *part, *colsum, *mask, *concat;
    cudaGetSymbolAddress((void**)&qh,     g_qh);
    cudaGetSymbolAddress((void**)&kh,     g_kh);
    cudaGetSymbolAddress((void**)&vh,     g_vh);
    cudaGetSymbolAddress((void**)&vtm,    g_vtm);
    cudaGetSymbolAddress((void**)&probs,  g_probs);
    cudaGetSymbolAddress((void**)&part,   g_part);
    cudaGetSymbolAddress((void**)&colsum, g_colsum);
    cudaGetSymbolAddress((void**)&mask,   g_mask);
    cudaGetSymbolAddress((void**)&concat, g_concat);

    dim3 gproj(DD / 128, (BB * SS) / 128, 1);

    // Selection-critical path: fp32 FFMA (matches R1 behavior exactly)
    sgemm_nt<<<gproj, 256>>>(q, Wq, qh, bq, DD, DD, DD, 0, 0, 0, 0, 1.f, 1);
    sgemm_nt<<<gproj, 256>>>(k, Wk, kh, bk, DD, DD, DD, 0, 0, 0, 0, 1.f, 1);

    // Value path: V projection on tensor cores (3xTF32)
    mma_gemm3<128><<<gproj, 256>>>(v, Wv, vh, bv, DD, DD, DD, 0, 0, 0, 0, 1.f, 1);

    // Scores: fp32 FFMA, batched 2048x2048x64 per (b,h), alpha = 1/8
    dim3 gsc(SS / 128, SS / 128, BHN);
    sgemm_nt<<<gsc, 256>>>(qh, kh, probs, nullptr, DK, DK, DK, SS,
                           (long long)SS * DK, (long long)SS * DK,
                           (long long)SS * SS, 0.125f, 0);

    // Fused softmax + colsum partials, then tiny reduce
    softmax_colsum_kernel<<<dim3(32, BHN), 256>>>(probs, part);
    colsum_reduce_kernel<<<dim3(SS / 256, BHN), 256>>>(part, colsum);

    // Top-k threshold -> column mask
    topk_mask_kernel<<<BHN, 1024>>>(colsum, mask);

    // Masked V transpose: vtm[bh][d][s]
    vt_mask_kernel<<<dim3(SS / 32, DK / 32, BHN), 256>>>(vh, mask, vtm);

    // AV on tensor cores (3xTF32): per (b,h) 2048x64x2048 -> concat layout
    dim3 gav(1, SS / 128, BHN);
    mma_gemm3<64><<<gav, 256>>>(probs, vtm, concat, nullptr, SS, SS, SS, 0,
                                (long long)SS * SS, (long long)DK * SS, 0, 1.f, 3);

    // Output projection on tensor cores (3xTF32)
    mma_gemm3<128><<<gproj, 256>>>(concat, Wo, out, bo, DD, DD, DD, DD,
                                   0, 0, 0, 1.f, 0);
}

// round 7
// speedup vs baseline: 1.4742x; 1.3708x over previous
#include <cuda_runtime.h>
#include <cuda_fp16.h>
#include <math.h>

// Problem constants
#define BB   2
#define HH   16
#define SS   2048
#define DD   1024
#define DK   64
#define BHN  (BB*HH)      // 32
#define KEEP 1843         // int(2048*0.9)

typedef unsigned int u32;

// ---------------- scratch (device globals; no cudaMalloc allowed) ----------
__device__ float  g_qh[(size_t)BHN * SS * DK];      // [b,h,s,d]
__device__ float  g_kh[(size_t)BHN * SS * DK];
__device__ float  g_vh[(size_t)BHN * SS * DK];
__device__ __half g_vtmh[(size_t)BHN * DK * SS];    // masked V^T fp16 [b,h,d,s]
__device__ float  g_probs[(size_t)BHN * SS * SS];   // 512 MiB fp32 scores
__device__ __half g_probsh[(size_t)BHN * SS * SS];  // 256 MiB fp16 probs
__device__ float  g_part[(size_t)BHN * 32 * SS];    // colsum partials
__device__ float  g_colsum[BHN * SS];
__device__ float  g_mask[BHN * SS];
__device__ __half g_concath[(size_t)BB * SS * DD];  // fp16 concat [b,s,h*64+d]

// ============================================================================
// FFMA fp32 NT SGEMM (selection-critical path) — identical math to R1/R6.
// ============================================================================
__global__ __launch_bounds__(256, 2)
void sgemm_nt(const float* __restrict__ Ag, const float* __restrict__ Bg,
              float* __restrict__ Cg, const float* __restrict__ bias,
              int K, int lda, int ldb, int ldc,
              long long sA, long long sB, long long sC,
              float alpha, int mode)
{
    __shared__ float As[8][128];
    __shared__ float Bs[8][128];

    const float* A = Ag + (size_t)blockIdx.z * sA;
    const float* B = Bg + (size_t)blockIdx.z * sB;
    float*       C = Cg + (size_t)blockIdx.z * sC;

    const int m0 = blockIdx.y * 128;
    const int n0 = blockIdx.x * 128;
    const int tid = threadIdx.x;
    const int tx = tid & 15;
    const int ty = tid >> 4;
    const int lrow = tid >> 1;
    const int lcol = (tid & 1) * 4;

    float acc[8][8];
#pragma unroll
    for (int i = 0; i < 8; i++)
#pragma unroll
        for (int j = 0; j < 8; j++) acc[i][j] = 0.f;

    const float* Aptr = A + (size_t)(m0 + lrow) * lda + lcol;
    const float* Bptr = B + (size_t)(n0 + lrow) * ldb + lcol;

    for (int k0 = 0; k0 < K; k0 += 8) {
        float4 av = *(const float4*)(Aptr + k0);
        float4 bv = *(const float4*)(Bptr + k0);
        __syncthreads();
        As[lcol + 0][lrow] = av.x; As[lcol + 1][lrow] = av.y;
        As[lcol + 2][lrow] = av.z; As[lcol + 3][lrow] = av.w;
        Bs[lcol + 0][lrow] = bv.x; Bs[lcol + 1][lrow] = bv.y;
        Bs[lcol + 2][lrow] = bv.z; Bs[lcol + 3][lrow] = bv.w;
        __syncthreads();
#pragma unroll
        for (int kk = 0; kk < 8; kk++) {
            float a[8], b[8];
            *(float4*)(a)     = *(const float4*)&As[kk][ty * 8];
            *(float4*)(a + 4) = *(const float4*)&As[kk][ty * 8 + 4];
            *(float4*)(b)     = *(const float4*)&Bs[kk][tx * 8];
            *(float4*)(b + 4) = *(const float4*)&Bs[kk][tx * 8 + 4];
#pragma unroll
            for (int i = 0; i < 8; i++)
#pragma unroll
                for (int j = 0; j < 8; j++) acc[i][j] += a[i] * b[j];
        }
    }

    if (mode == 0) {
#pragma unroll
        for (int i = 0; i < 8; i++) {
            int m = m0 + ty * 8 + i;
            float out[8];
#pragma unroll
            for (int j = 0; j < 8; j++) {
                int n = n0 + tx * 8 + j;
                out[j] = acc[i][j] * alpha + (bias ? bias[n] : 0.f);
            }
            float* crow = C + (size_t)m * ldc + n0 + tx * 8;
            *(float4*)(crow)     = *(float4*)(out);
            *(float4*)(crow + 4) = *(float4*)(out + 4);
        }
    } else {
#pragma unroll
        for (int i = 0; i < 8; i++) {
            int m = m0 + ty * 8 + i;
            int b = m >> 11;
            int s = m & (SS - 1);
#pragma unroll
            for (int j = 0; j < 8; j++) {
                int n = n0 + tx * 8 + j;
                int h = n >> 6;
                int d = n & 63;
                C[(((size_t)(b * HH + h)) * SS + s) * DK + d] =
                    acc[i][j] * alpha + (bias ? bias[n] : 0.f);
            }
        }
    }
}

// ============================================================================
// 3xTF32 mma.sync NT GEMM (V projection): fp32-grade via hi/lo split.
// ============================================================================
static __device__ __forceinline__ u32 f2tf(float x) {
    u32 r;
    asm("cvt.rna.tf32.f32 %0, %1;" : "=r"(r) : "f"(x));
    return r;
}
static __device__ __forceinline__ void mma_tf32(float* d, const u32* a, const u32* b) {
    asm volatile(
        "mma.sync.aligned.m16n8k8.row.col.f32.tf32.tf32.f32 "
        "{%0,%1,%2,%3}, {%4,%5,%6,%7}, {%8,%9}, {%0,%1,%2,%3};"
        : "+f"(d[0]), "+f"(d[1]), "+f"(d[2]), "+f"(d[3])
        : "r"(a[0]), "r"(a[1]), "r"(a[2]), "r"(a[3]), "r"(b[0]), "r"(b[1]));
}

__global__ __launch_bounds__(256)
void mma_gemm3_proj(const float* __restrict__ Ag, const float* __restrict__ Bg,
                    float* __restrict__ Cg, const float* __restrict__ bias,
                    int K, int lda, int ldb)
{
    __shared__ u32 Ash[128][20];
    __shared__ u32 Asl[128][20];
    __shared__ u32 Bsh[128][20];
    __shared__ u32 Bsl[128][20];

    const int tid  = threadIdx.x;
    const int wid  = tid >> 5;
    const int lane = tid & 31;
    const int wm   = wid & 1;
    const int wn   = wid >> 1;
    const int qid  = lane >> 2;
    const int rid  = lane & 3;

    const int m0 = blockIdx.y * 128;
    const int n0 = blockIdx.x * 128;

    float acc[4][4][4];
#pragma unroll
    for (int i = 0; i < 4; i++)
#pragma unroll
        for (int j = 0; j < 4; j++)
#pragma unroll
            for (int t = 0; t < 4; t++) acc[i][j][t] = 0.f;

    const int nc = K >> 4;
    for (int c = 0; c < nc; c++) {
        const int k0 = c << 4;
        float4 va[2], vb[2];
#pragma unroll
        for (int i = 0; i < 2; i++) {
            int idx = tid + i * 256;
            int r = idx >> 2, cc = (idx & 3) << 2;
            va[i] = *(const float4*)(Ag + (size_t)(m0 + r) * lda + k0 + cc);
            vb[i] = *(const float4*)(Bg + (size_t)(n0 + r) * ldb + k0 + cc);
        }
        __syncthreads();
#pragma unroll
        for (int i = 0; i < 2; i++) {
            int idx = tid + i * 256;
            int r = idx >> 2, cc = (idx & 3) << 2;
            float xa[4] = {va[i].x, va[i].y, va[i].z, va[i].w};
            float xb[4] = {vb[i].x, vb[i].y, vb[i].z, vb[i].w};
#pragma unroll
            for (int t = 0; t < 4; t++) {
                u32 h = f2tf(xa[t]);
                Ash[r][cc + t] = h;
                Asl[r][cc + t] = f2tf(xa[t] - __uint_as_float(h));
                u32 g = f2tf(xb[t]);
                Bsh[r][cc + t] = g;
                Bsl[r][cc + t] = f2tf(xb[t] - __uint_as_float(g));
            }
        }
        __syncthreads();

#pragma unroll
        for (int kk = 0; kk < 16; kk += 8) {
            u32 af[4][4], bfh[4][2], bfl[4][2];
#pragma unroll
            for (int mt = 0; mt < 4; mt++) {
                int row = wm * 64 + mt * 16 + qid;
                af[mt][0] = Ash[row    ][kk + rid];
                af[mt][1] = Ash[row + 8][kk + rid];
                af[mt][2] = Ash[row    ][kk + 4 + rid];
                af[mt][3] = Ash[row + 8][kk + 4 + rid];
            }
#pragma unroll
            for (int nt = 0; nt < 4; nt++) {
                int col = wn * 32 + nt * 8 + qid;
                bfh[nt][0] = Bsh[col][kk + rid];
                bfh[nt][1] = Bsh[col][kk + 4 + rid];
                bfl[nt][0] = Bsl[col][kk + rid];
                bfl[nt][1] = Bsl[col][kk + 4 + rid];
            }
#pragma unroll
            for (int mt = 0; mt < 4; mt++)
#pragma unroll
                for (int nt = 0; nt < 4; nt++) {
                    mma_tf32(acc[mt][nt], af[mt], bfh[nt]);
                    mma_tf32(acc[mt][nt], af[mt], bfl[nt]);
                }
#pragma unroll
            for (int mt = 0; mt < 4; mt++) {
                int row = wm * 64 + mt * 16 + qid;
                af[mt][0] = Asl[row    ][kk + rid];
                af[mt][1] = Asl[row + 8][kk + rid];
                af[mt][2] = Asl[row    ][kk + 4 + rid];
                af[mt][3] = Asl[row + 8][kk + 4 + rid];
            }
#pragma unroll
            for (int mt = 0; mt < 4; mt++)
#pragma unroll
                for (int nt = 0; nt < 4; nt++)
                    mma_tf32(acc[mt][nt], af[mt], bfh[nt]);
        }
    }

    // head-scatter epilogue into [b,h,s,d]
#pragma unroll
    for (int mt = 0; mt < 4; mt++) {
        int r0 = m0 + wm * 64 + mt * 16 + qid;
        int r1 = r0 + 8;
#pragma unroll
        for (int nt = 0; nt < 4; nt++) {
            int cb = n0 + wn * 32 + nt * 8 + rid * 2;
            float b0 = bias[cb], b1 = bias[cb + 1];
            float v0 = acc[mt][nt][0] + b0;
            float v1 = acc[mt][nt][1] + b1;
            float v2 = acc[mt][nt][2] + b0;
            float v3 = acc[mt][nt][3] + b1;
            int h = cb >> 6, d = cb & 63;
            int b0i = r0 >> 11, s0i = r0 & (SS - 1);
            int b1i = r1 >> 11, s1i = r1 & (SS - 1);
            *(float2*)(Cg + (((size_t)(b0i * HH + h)) * SS + s0i) * DK + d) =
                make_float2(v0, v1);
            *(float2*)(Cg + (((size_t)(b1i * HH + h)) * SS + s1i) * DK + d) =
                make_float2(v2, v3);
        }
    }
}

// ============================================================================
// fp16 m16n8k16 NT GEMM (value path). A fp16, B fp16 or fp32(cvt), f32 acc.
// CTA 128 x NT, BK=32, 8 warps 2(m)x4(n).
// mode 3: AV -> fp16 concat scatter (z=(b,h)); mode 0: fp32 C + bias.
// ============================================================================
static __device__ __forceinline__ void mma_f16(float* d, const u32* a, const u32* b) {
    asm volatile(
        "mma.sync.aligned.m16n8k16.row.col.f32.f16.f16.f32 "
        "{%0,%1,%2,%3}, {%4,%5,%6,%7}, {%8,%9}, {%0,%1,%2,%3};"
        : "+f"(d[0]), "+f"(d[1]), "+f"(d[2]), "+f"(d[3])
        : "r"(a[0]), "r"(a[1]), "r"(a[2]), "r"(a[3]), "r"(b[0]), "r"(b[1]));
}

template<int NT, bool B_F32>
__global__ __launch_bounds__(256)
void hgemm_nt(const __half* __restrict__ Ag, const void* __restrict__ Bv,
              float* __restrict__ Cf, __half* __restrict__ Ch,
              const float* __restrict__ bias,
              int K, int lda, int ldb, int ldc,
              long long sA, long long sB,
              int mode)
{
    __shared__ __half As[128][56];
    __shared__ __half Bs[NT][56];

    const int tid  = threadIdx.x;
    const int wid  = tid >> 5;
    const int lane = tid & 31;
    const int wm   = wid & 1;
    const int wn   = wid >> 1;
    const int qid  = lane >> 2;
    const int rid  = lane & 3;

    constexpr int WN  = NT / 4;      // 32 or 16
    constexpr int NFR = WN / 8;      // 4 or 2

    const __half* A = Ag + (size_t)blockIdx.z * sA;
    const int m0 = blockIdx.y * 128;
    const int n0 = blockIdx.x * NT;

    float acc[4][NFR][4];
#pragma unroll
    for (int i = 0; i < 4; i++)
#pragma unroll
        for (int j = 0; j < NFR; j++)
#pragma unroll
            for (int t = 0; t < 4; t++) acc[i][j][t] = 0.f;

    const int nc = K >> 5;
    for (int c = 0; c < nc; c++) {
        const int k0 = c << 5;
        // A: 128x32 halves = 512 uint4 -> 2 per thread
        uint4 va[2];
#pragma unroll
        for (int i = 0; i < 2; i++) {
            int idx = tid + i * 256;
            int r = idx >> 2, seg = (idx & 3) << 3;
            va[i] = *(const uint4*)(A + (size_t)(m0 + r) * lda + k0 + seg);
        }
        if (B_F32) {
            const float* B = (const float*)Bv + (size_t)blockIdx.z * sB;
            float4 vb[(NT * 32) / (4 * 256)];
            constexpr int BI = (NT * 32) / (4 * 256);
#pragma unroll
            for (int i = 0; i < BI; i++) {
                int idx = tid + i * 256;
                int r = idx >> 3, seg = (idx & 7) << 2;
                vb[i] = *(const float4*)(B + (size_t)(n0 + r) * ldb + k0 + seg);
            }
            __syncthreads();
#pragma unroll
            for (int i = 0; i < 2; i++) {
                int idx = tid + i * 256;
                int r = idx >> 2, seg = (idx & 3) << 3;
                *(uint4*)&As[r][seg] = va[i];
            }
#pragma unroll
            for (int i = 0; i < BI; i++) {
                int idx = tid + i * 256;
                int r = idx >> 3, seg = (idx & 7) << 2;
                __half2 h0 = __floats2half2_rn(vb[i].x, vb[i].y);
                __half2 h1 = __floats2half2_rn(vb[i].z, vb[i].w);
                *(__half2*)&Bs[r][seg]     = h0;
                *(__half2*)&Bs[r][seg + 2] = h1;
            }
        } else {
            const __half* B = (const __half*)Bv + (size_t)blockIdx.z * sB;
            constexpr int BI = (NT * 32) / (8 * 256) > 0 ? (NT * 32) / (8 * 256) : 1;
            uint4 vb[BI];
#pragma unroll
            for (int i = 0; i < BI; i++) {
                int idx = tid + i * 256;
                int r = idx >> 2, seg = (idx & 3) << 3;
                vb[i] = *(const uint4*)(B + (size_t)(n0 + r) * ldb + k0 + seg);
            }
            __syncthreads();
#pragma unroll
            for (int i = 0; i < 2; i++) {
                int idx = tid + i * 256;
                int r = idx >> 2, seg = (idx & 3) << 3;
                *(uint4*)&As[r][seg] = va[i];
            }
#pragma unroll
            for (int i = 0; i < BI; i++) {
                int idx = tid + i * 256;
                int r = idx >> 2, seg = (idx & 3) << 3;
                *(uint4*)&Bs[r][seg] = vb[i];
            }
        }
        __syncthreads();

#pragma unroll
        for (int kk = 0; kk < 32; kk += 16) {
            u32 af[4][4], bf[NFR][2];
#pragma unroll
            for (int mt = 0; mt < 4; mt++) {
                int row = wm * 64 + mt * 16 + qid;
                af[mt][0] = *(const u32*)&As[row    ][kk + rid * 2];
                af[mt][1] = *(const u32*)&As[row + 8][kk + rid * 2];
                af[mt][2] = *(const u32*)&As[row    ][kk + rid * 2 + 8];
                af[mt][3] = *(const u32*)&As[row + 8][kk + rid * 2 + 8];
            }
#pragma unroll
            for (int nt = 0; nt < NFR; nt++) {
                int col = wn * WN + nt * 8 + qid;
                bf[nt][0] = *(const u32*)&Bs[col][kk + rid * 2];
                bf[nt][1] = *(const u32*)&Bs[col][kk + rid * 2 + 8];
            }
#pragma unroll
            for (int mt = 0; mt < 4; mt++)
#pragma unroll
                for (int nt = 0; nt < NFR; nt++)
                    mma_f16(acc[mt][nt], af[mt], bf[nt]);
        }
    }

    // ---------------- epilogue ----------------
#pragma unroll
    for (int mt = 0; mt < 4; mt++) {
        int r0 = m0 + wm * 64 + mt * 16 + qid;
        int r1 = r0 + 8;
#pragma unroll
        for (int nt = 0; nt < NFR; nt++) {
            int cb = n0 + wn * WN + nt * 8 + rid * 2;
            float v0 = acc[mt][nt][0];
            float v1 = acc[mt][nt][1];
            float v2 = acc[mt][nt][2];
            float v3 = acc[mt][nt][3];
            if (mode == 0) {
                float b0 = bias[cb], b1 = bias[cb + 1];
                *(float2*)(Cf + (size_t)r0 * ldc + cb) = make_float2(v0 + b0, v1 + b1);
                *(float2*)(Cf + (size_t)r1 * ldc + cb) = make_float2(v2 + b0, v3 + b1);
            } else { // mode 3: fp16 concat
                int z = blockIdx.z, b = z >> 4, h = z & 15;
                *(__half2*)(Ch + ((size_t)b * SS + r0) * DD + h * DK + cb) =
                    __floats2half2_rn(v0, v1);
                *(__half2*)(Ch + ((size_t)b * SS + r1) * DD + h * DK + cb) =
                    __floats2half2_rn(v2, v3);
            }
        }
    }
}

// ============================================================================
// Fused softmax + colsum partials; writes fp16 probs. Block = 64 rows.
// Thread handles 8 CONTIGUOUS elements (enables uint4 fp16 store).
// ============================================================================
__global__ __launch_bounds__(256)
void softmax_colsum_kernel(const float* __restrict__ scores,
                           __half* __restrict__ probsh,
                           float* __restrict__ part)
{
    __shared__ float redA[8];
    __shared__ float redB[8];
    const int rb = blockIdx.x;   // 0..31
    const int bh = blockIdx.y;
    const int tid = threadIdx.x;
    const int wid = tid >> 5, lane = tid & 31;

    float cs[8];
#pragma unroll
    for (int i = 0; i < 8; i++) cs[i] = 0.f;

    for (int r = 0; r < 64; r++) {
        const float* row = scores + ((size_t)bh * SS + rb * 64 + r) * SS + tid * 8;
        float x[8];
        *(float4*)(x)     = *(const float4*)(row);
        *(float4*)(x + 4) = *(const float4*)(row + 4);

        float m = x[0];
#pragma unroll
        for (int i = 1; i < 8; i++) m = fmaxf(m, x[i]);
#pragma unroll
        for (int o = 16; o > 0; o >>= 1)
            m = fmaxf(m, __shfl_xor_sync(0xFFFFFFFF, m, o));
        if (lane == 0) redA[wid] = m;
        __syncthreads();
        m = redA[0];
#pragma unroll
        for (int w = 1; w < 8; w++) m = fmaxf(m, redA[w]);

        float s = 0.f;
#pragma unroll
        for (int i = 0; i < 8; i++) {
            x[i] = __expf(x[i] - m);
            s += x[i];
        }
#pragma unroll
        for (int o = 16; o > 0; o >>= 1)
            s += __shfl_xor_sync(0xFFFFFFFF, s, o);
        if (lane == 0) redB[wid] = s;
        __syncthreads();
        s = redB[0];
#pragma unroll
        for (int w = 1; w < 8; w++) s += redB[w];
        float inv = 1.0f / s;

        __half2 h[4];
#pragma unroll
        for (int i = 0; i < 8; i += 2) {
            float p0 = x[i] * inv, p1 = x[i + 1] * inv;
            cs[i] += p0; cs[i + 1] += p1;
            h[i >> 1] = __floats2half2_rn(p0, p1);
        }
        *(uint4*)(probsh + ((size_t)bh * SS + rb * 64 + r) * SS + tid * 8) =
            *(uint4*)h;
        __syncthreads();
    }
#pragma unroll
    for (int i = 0; i < 8; i++)
        part[((size_t)bh * 32 + rb) * SS + tid * 8 + i] = cs[i];
}

__global__ void colsum_reduce_kernel(const float* __restrict__ part,
                                     float* __restrict__ colsum)
{
    const int k = blockIdx.x * 256 + threadIdx.x;
    const int bh = blockIdx.y;
    float s = 0.f;
#pragma unroll
    for (int rb = 0; rb < 32; rb++)
        s += part[((size_t)bh * 32 + rb) * SS + k];
    colsum[bh * SS + k] = s;
}

// ============================================================================
// Top-k mask via bitonic sort of the 2048 column sums.
// ============================================================================
__global__ void topk_mask_kernel(const float* __restrict__ colsum,
                                 float* __restrict__ mask)
{
    __shared__ float s[SS];
    const int bh = blockIdx.x;
    const int tid = threadIdx.x; // 1024
    const float* cs = colsum + bh * SS;
    s[tid] = cs[tid];
    s[tid + 1024] = cs[tid + 1024];
    __syncthreads();

    for (int ksz = 2; ksz <= SS; ksz <<= 1) {
        for (int j = ksz >> 1; j > 0; j >>= 1) {
            for (int i = tid; i < SS; i += 1024) {
                int p = i ^ j;
                if (p > i) {
                    bool up = ((i & ksz) == 0);
                    float a = s[i], b = s[p];
                    if ((a > b) == up) { s[i] = b; s[p] = a; }
                }
            }
            __syncthreads();
        }
    }
    float thr = s[SS - KEEP];
    mask[bh * SS + tid]        = (cs[tid]        >= thr) ? 1.f : 0.f;
    mask[bh * SS + tid + 1024] = (cs[tid + 1024] >= thr) ? 1.f : 0.f;
}

// ============================================================================
// Masked transpose to fp16: vtmh[bh][d][s] = fp16(vh[bh][s][d] * mask[bh][s])
// ============================================================================
__global__ void vt_mask_kernel(const float* __restrict__ vh,
                               const float* __restrict__ mask,
                               __half* __restrict__ vtmh)
{
    __shared__ float t[32][33];
    const int bh = blockIdx.z;
    const int s0 = blockIdx.x * 32;
    const int d0 = blockIdx.y * 32;
    const int lx = threadIdx.x & 31;
    const int ly = threadIdx.x >> 5;
    for (int i = ly; i < 32; i += 8)
        t[i][lx] = vh[((size_t)bh * SS + s0 + i) * DK + d0 + lx] * mask[bh * SS + s0 + i];
    __syncthreads();
    for (int i = ly; i < 32; i += 8)
        vtmh[((size_t)bh * DK + d0 + i) * SS + s0 + lx] = __float2half_rn(t[lx][i]);
}

// ---------------------------------------------------------------------------
extern "C" void kernel_launch(void* const* d_in, const int* in_sizes, int n_in,
                              void* d_out, int out_size)
{
    (void)in_sizes; (void)n_in; (void)out_size;
    const float* q  = (const float*)d_in[0];
    const float* k  = (const float*)d_in[1];
    const float* v  = (const float*)d_in[2];
    const float* Wq = (const float*)d_in[3];
    const float* bq = (const float*)d_in[4];
    const float* Wk = (const float*)d_in[5];
    const float* bk = (const float*)d_in[6];
    const float* Wv = (const float*)d_in[7];
    const float* bv = (const float*)d_in[8];
    const float* Wo = (const float*)d_in[9];
    const float* bo = (const float*)d_in[10];
    float* out = (float*)d_out;

    float *qh, *kh, *vh, *probs, *part, *colsum, *mask;
    __half *vtmh, *probsh, *concath;
    cudaGetSymbolAddress((void**)&qh,      g_qh);
    cudaGetSymbolAddress((void**)&kh,      g_kh);
    cudaGetSymbolAddress((void**)&vh,      g_vh);
    cudaGetSymbolAddress((void**)&vtmh,    g_vtmh);
    cudaGetSymbolAddress((void**)&probs,   g_probs);
    cudaGetSymbolAddress((void**)&probsh,  g_probsh);
    cudaGetSymbolAddress((void**)&part,    g_part);
    cudaGetSymbolAddress((void**)&colsum,  g_colsum);
    cudaGetSymbolAddress((void**)&mask,    g_mask);
    cudaGetSymbolAddress((void**)&concath, g_concath);

    dim3 gproj(DD / 128, (BB * SS) / 128, 1);

    // Selection-critical path: fp32 FFMA (matches R1/R6 exactly)
    sgemm_nt<<<gproj, 256>>>(q, Wq, qh, bq, DD, DD, DD, 0, 0, 0, 0, 1.f, 1);
    sgemm_nt<<<gproj, 256>>>(k, Wk, kh, bk, DD, DD, DD, 0, 0, 0, 0, 1.f, 1);

    // V projection: 3xTF32 (fp32-grade), head-scattered
    mma_gemm3_proj<<<gproj, 256>>>(v, Wv, vh, bv, DD, DD, DD);

    // Scores: fp32 FFMA, batched 2048x2048x64 per (b,h), alpha = 1/8
    dim3 gsc(SS / 128, SS / 128, BHN);
    sgemm_nt<<<gsc, 256>>>(qh, kh, probs, nullptr, DK, DK, DK, SS,
                           (long long)SS * DK, (long long)SS * DK,
                           (long long)SS * SS, 0.125f, 0);

    // Fused softmax + colsum partials (fp16 probs out), then reduce
    softmax_colsum_kernel<<<dim3(32, BHN), 256>>>(probs, probsh, part);
    colsum_reduce_kernel<<<dim3(SS / 256, BHN), 256>>>(part, colsum);

    // Top-k threshold -> column mask
    topk_mask_kernel<<<BHN, 1024>>>(colsum, mask);

    // Masked V transpose -> fp16 vtmh[bh][d][s]
    vt_mask_kernel<<<dim3(SS / 32, DK / 32, BHN), 256>>>(vh, mask, vtmh);

    // AV (fp16 mma): per (b,h) 2048x64x2048 -> fp16 concat
    dim3 gav(1, SS / 128, BHN);
    hgemm_nt<64, false><<<gav, 256>>>(probsh, vtmh, nullptr, concath, nullptr,
                                      SS, SS, SS, 0,
                                      (long long)SS * SS, (long long)DK * SS, 3);

    // Output projection (fp16 mma, Wo cvt on load): fp32 out + bias
    hgemm_nt<128, true><<<gproj, 256>>>(concath, Wo, out, nullptr, bo,
                                        DD, DD, DD, DD, 0, 0, 0);
}

// round 8
// speedup vs baseline: 1.6189x; 1.0982x over previous
#include <cuda_runtime.h>
#include <cuda_fp16.h>
#include <math.h>

// Problem constants
#define BB   2
#define HH   16
#define SS   2048
#define DD   1024
#define DK   64
#define BHN  (BB*HH)      // 32
#define KEEP 1843         // int(2048*0.9)

typedef unsigned int u32;

// ---------------- scratch (device globals; no cudaMalloc allowed) ----------
__device__ float  g_qh[(size_t)BHN * SS * DK];      // [b,h,s,d]
__device__ float  g_kh[(size_t)BHN * SS * DK];
__device__ float  g_vh[(size_t)BHN * SS * DK];
__device__ __half g_vtmh[(size_t)BHN * DK * SS];    // masked V^T fp16 [b,h,d,s]
__device__ float  g_probs[(size_t)BHN * SS * SS];   // 512 MiB fp32 scores
__device__ __half g_probsh[(size_t)BHN * SS * SS];  // 256 MiB fp16 probs
__device__ float  g_part[(size_t)BHN * 32 * SS];    // colsum partials
__device__ float  g_mask[BHN * SS];
__device__ __half g_concath[(size_t)BB * SS * DD];  // fp16 concat [b,s,h*64+d]

// ============================================================================
// FFMA fp32 NT GEMM body (selection-critical path), double-buffered smem.
// Accumulation order identical to R1/R6/R7 => bitwise-same scores/selection.
// MODE 0: row-major C (ldc); MODE 1: head-scatter [b,h,s,d].
// ============================================================================
template<int MODE>
__device__ __forceinline__ void ffma_tile(
    const float* __restrict__ A, const float* __restrict__ B,
    float* __restrict__ C, const float* __restrict__ bias,
    int K, int lda, int ldb, int ldc, float alpha,
    float As[2][8][128], float Bs[2][8][128])
{
    const int m0 = blockIdx.y * 128;
    const int n0 = blockIdx.x * 128;
    const int tid = threadIdx.x;
    const int tx = tid & 15;
    const int ty = tid >> 4;
    const int lrow = tid >> 1;
    const int lcol = (tid & 1) * 4;

    float acc[8][8];
#pragma unroll
    for (int i = 0; i < 8; i++)
#pragma unroll
        for (int j = 0; j < 8; j++) acc[i][j] = 0.f;

    const float* Aptr = A + (size_t)(m0 + lrow) * lda + lcol;
    const float* Bptr = B + (size_t)(n0 + lrow) * ldb + lcol;

    // prologue: chunk 0 -> buffer 0
    {
        float4 av = *(const float4*)(Aptr);
        float4 bv = *(const float4*)(Bptr);
        As[0][lcol + 0][lrow] = av.x; As[0][lcol + 1][lrow] = av.y;
        As[0][lcol + 2][lrow] = av.z; As[0][lcol + 3][lrow] = av.w;
        Bs[0][lcol + 0][lrow] = bv.x; Bs[0][lcol + 1][lrow] = bv.y;
        Bs[0][lcol + 2][lrow] = bv.z; Bs[0][lcol + 3][lrow] = bv.w;
    }
    __syncthreads();

    int buf = 0;
    for (int k0 = 8; k0 < K; k0 += 8) {
        float4 av = *(const float4*)(Aptr + k0);
        float4 bv = *(const float4*)(Bptr + k0);
        const int nb = buf ^ 1;
        As[nb][lcol + 0][lrow] = av.x; As[nb][lcol + 1][lrow] = av.y;
        As[nb][lcol + 2][lrow] = av.z; As[nb][lcol + 3][lrow] = av.w;
        Bs[nb][lcol + 0][lrow] = bv.x; Bs[nb][lcol + 1][lrow] = bv.y;
        Bs[nb][lcol + 2][lrow] = bv.z; Bs[nb][lcol + 3][lrow] = bv.w;
#pragma unroll
        for (int kk = 0; kk < 8; kk++) {
            float a[8], b[8];
            *(float4*)(a)     = *(const float4*)&As[buf][kk][ty * 8];
            *(float4*)(a + 4) = *(const float4*)&As[buf][kk][ty * 8 + 4];
            *(float4*)(b)     = *(const float4*)&Bs[buf][kk][tx * 8];
            *(float4*)(b + 4) = *(const float4*)&Bs[buf][kk][tx * 8 + 4];
#pragma unroll
            for (int i = 0; i < 8; i++)
#pragma unroll
                for (int j = 0; j < 8; j++) acc[i][j] += a[i] * b[j];
        }
        __syncthreads();
        buf = nb;
    }
    // final chunk
#pragma unroll
    for (int kk = 0; kk < 8; kk++) {
        float a[8], b[8];
        *(float4*)(a)     = *(const float4*)&As[buf][kk][ty * 8];
        *(float4*)(a + 4) = *(const float4*)&As[buf][kk][ty * 8 + 4];
        *(float4*)(b)     = *(const float4*)&Bs[buf][kk][tx * 8];
        *(float4*)(b + 4) = *(const float4*)&Bs[buf][kk][tx * 8 + 4];
#pragma unroll
        for (int i = 0; i < 8; i++)
#pragma unroll
            for (int j = 0; j < 8; j++) acc[i][j] += a[i] * b[j];
    }

    if (MODE == 0) {
#pragma unroll
        for (int i = 0; i < 8; i++) {
            int m = m0 + ty * 8 + i;
            float out[8];
#pragma unroll
            for (int j = 0; j < 8; j++) {
                int n = n0 + tx * 8 + j;
                out[j] = acc[i][j] * alpha + (bias ? bias[n] : 0.f);
            }
            float* crow = C + (size_t)m * ldc + n0 + tx * 8;
            *(float4*)(crow)     = *(float4*)(out);
            *(float4*)(crow + 4) = *(float4*)(out + 4);
        }
    } else {
#pragma unroll
        for (int i = 0; i < 8; i++) {
            int m = m0 + ty * 8 + i;
            int b = m >> 11;
            int s = m & (SS - 1);
#pragma unroll
            for (int j = 0; j < 8; j++) {
                int n = n0 + tx * 8 + j;
                int h = n >> 6;
                int d = n & 63;
                C[(((size_t)(b * HH + h)) * SS + s) * DK + d] =
                    acc[i][j] * alpha + (bias ? bias[n] : 0.f);
            }
        }
    }
}

// Q and K projections in one launch (blockIdx.z selects).
__global__ __launch_bounds__(256, 2)
void sgemm_qk(const float* __restrict__ q,  const float* __restrict__ Wq,
              const float* __restrict__ bq, float* __restrict__ qh,
              const float* __restrict__ k,  const float* __restrict__ Wk,
              const float* __restrict__ bk, float* __restrict__ kh)
{
    __shared__ float As[2][8][128];
    __shared__ float Bs[2][8][128];
    const float* A  = blockIdx.z ? k  : q;
    const float* B  = blockIdx.z ? Wk : Wq;
    const float* bi = blockIdx.z ? bk : bq;
    float*       C  = blockIdx.z ? kh : qh;
    ffma_tile<1>(A, B, C, bi, DD, DD, DD, 0, 1.f, As, Bs);
}

// Scores: batched per (b,h), z = bh.
__global__ __launch_bounds__(256, 2)
void sgemm_scores(const float* __restrict__ qh, const float* __restrict__ kh,
                  float* __restrict__ probs)
{
    __shared__ float As[2][8][128];
    __shared__ float Bs[2][8][128];
    const size_t z = blockIdx.z;
    ffma_tile<0>(qh + z * SS * DK, kh + z * SS * DK, probs + z * SS * SS,
                 nullptr, DK, DK, DK, SS, 0.125f, As, Bs);
}

// ============================================================================
// fp16x3 split NT GEMM (V projection, value path): 22-bit accurate.
// x = hi(fp16) + lo(fp16); acc += Ah*Bh + Ah*Bl + Al*Bh. CTA 128x128, BK=32.
// Epilogue: head-scatter [b,h,s,d] + bias.
// ============================================================================
static __device__ __forceinline__ void mma_f16(float* d, const u32* a, const u32* b) {
    asm volatile(
        "mma.sync.aligned.m16n8k16.row.col.f32.f16.f16.f32 "
        "{%0,%1,%2,%3}, {%4,%5,%6,%7}, {%8,%9}, {%0,%1,%2,%3};"
        : "+f"(d[0]), "+f"(d[1]), "+f"(d[2]), "+f"(d[3])
        : "r"(a[0]), "r"(a[1]), "r"(a[2]), "r"(a[3]), "r"(b[0]), "r"(b[1]));
}

__global__ __launch_bounds__(256)
void hgemm3_proj(const float* __restrict__ Ag, const float* __restrict__ Bg,
                 float* __restrict__ Cg, const float* __restrict__ bias)
{
    __shared__ __half Ah[128][40];
    __shared__ __half Al[128][40];
    __shared__ __half Bh[128][40];
    __shared__ __half Bl[128][40];

    const int tid  = threadIdx.x;
    const int wid  = tid >> 5;
    const int lane = tid & 31;
    const int wm   = wid & 1;
    const int wn   = wid >> 1;
    const int qid  = lane >> 2;
    const int rid  = lane & 3;

    const int m0 = blockIdx.y * 128;
    const int n0 = blockIdx.x * 128;

    float acc[4][4][4];
#pragma unroll
    for (int i = 0; i < 4; i++)
#pragma unroll
        for (int j = 0; j < 4; j++)
#pragma unroll
            for (int t = 0; t < 4; t++) acc[i][j][t] = 0.f;

    for (int c = 0; c < DD / 32; c++) {
        const int k0 = c << 5;
        float4 va[4], vb[4];
#pragma unroll
        for (int i = 0; i < 4; i++) {
            int idx = tid + i * 256;            // 0..1023
            int r = idx >> 3, cc = (idx & 7) << 2;
            va[i] = *(const float4*)(Ag + (size_t)(m0 + r) * DD + k0 + cc);
            vb[i] = *(const float4*)(Bg + (size_t)(n0 + r) * DD + k0 + cc);
        }
        __syncthreads();
#pragma unroll
        for (int i = 0; i < 4; i++) {
            int idx = tid + i * 256;
            int r = idx >> 3, cc = (idx & 7) << 2;
            float xa[4] = {va[i].x, va[i].y, va[i].z, va[i].w};
            float xb[4] = {vb[i].x, vb[i].y, vb[i].z, vb[i].w};
#pragma unroll
            for (int t = 0; t < 4; t++) {
                __half h = __float2half_rn(xa[t]);
                Ah[r][cc + t] = h;
                Al[r][cc + t] = __float2half_rn(xa[t] - __half2float(h));
                __half g = __float2half_rn(xb[t]);
                Bh[r][cc + t] = g;
                Bl[r][cc + t] = __float2half_rn(xb[t] - __half2float(g));
            }
        }
        __syncthreads();

#pragma unroll
        for (int kk = 0; kk < 32; kk += 16) {
            u32 ah[4][4], al[4][4], bh[4][2], bl[4][2];
#pragma unroll
            for (int mt = 0; mt < 4; mt++) {
                int row = wm * 64 + mt * 16 + qid;
                ah[mt][0] = *(const u32*)&Ah[row    ][kk + rid * 2];
                ah[mt][1] = *(const u32*)&Ah[row + 8][kk + rid * 2];
                ah[mt][2] = *(const u32*)&Ah[row    ][kk + rid * 2 + 8];
                ah[mt][3] = *(const u32*)&Ah[row + 8][kk + rid * 2 + 8];
                al[mt][0] = *(const u32*)&Al[row    ][kk + rid * 2];
                al[mt][1] = *(const u32*)&Al[row + 8][kk + rid * 2];
                al[mt][2] = *(const u32*)&Al[row    ][kk + rid * 2 + 8];
                al[mt][3] = *(const u32*)&Al[row + 8][kk + rid * 2 + 8];
            }
#pragma unroll
            for (int nt = 0; nt < 4; nt++) {
                int col = wn * 32 + nt * 8 + qid;
                bh[nt][0] = *(const u32*)&Bh[col][kk + rid * 2];
                bh[nt][1] = *(const u32*)&Bh[col][kk + rid * 2 + 8];
                bl[nt][0] = *(const u32*)&Bl[col][kk + rid * 2];
                bl[nt][1] = *(const u32*)&Bl[col][kk + rid * 2 + 8];
            }
#pragma unroll
            for (int mt = 0; mt < 4; mt++)
#pragma unroll
                for (int nt = 0; nt < 4; nt++) {
                    mma_f16(acc[mt][nt], ah[mt], bh[nt]);
                    mma_f16(acc[mt][nt], ah[mt], bl[nt]);
                    mma_f16(acc[mt][nt], al[mt], bh[nt]);
                }
        }
        __syncthreads();
    }

    // head-scatter epilogue into [b,h,s,d]
#pragma unroll
    for (int mt = 0; mt < 4; mt++) {
        int r0 = m0 + wm * 64 + mt * 16 + qid;
        int r1 = r0 + 8;
#pragma unroll
        for (int nt = 0; nt < 4; nt++) {
            int cb = n0 + wn * 32 + nt * 8 + rid * 2;
            float b0 = bias[cb], b1 = bias[cb + 1];
            float v0 = acc[mt][nt][0] + b0;
            float v1 = acc[mt][nt][1] + b1;
            float v2 = acc[mt][nt][2] + b0;
            float v3 = acc[mt][nt][3] + b1;
            int h = cb >> 6, d = cb & 63;
            int b0i = r0 >> 11, s0i = r0 & (SS - 1);
            int b1i = r1 >> 11, s1i = r1 & (SS - 1);
            *(float2*)(Cg + (((size_t)(b0i * HH + h)) * SS + s0i) * DK + d) =
                make_float2(v0, v1);
            *(float2*)(Cg + (((size_t)(b1i * HH + h)) * SS + s1i) * DK + d) =
                make_float2(v2, v3);
        }
    }
}

// ============================================================================
// fp16 m16n8k16 NT GEMM (value path). A fp16, B fp16 or fp32(cvt), f32 acc.
// mode 3: AV -> fp16 concat scatter (z=(b,h)); mode 0: fp32 C + bias.
// ============================================================================
template<int NT, bool B_F32>
__global__ __launch_bounds__(256)
void hgemm_nt(const __half* __restrict__ Ag, const void* __restrict__ Bv,
              float* __restrict__ Cf, __half* __restrict__ Ch,
              const float* __restrict__ bias,
              int K, int lda, int ldb, int ldc,
              long long sA, long long sB,
              int mode)
{
    __shared__ __half As[128][56];
    __shared__ __half Bs[NT][56];

    const int tid  = threadIdx.x;
    const int wid  = tid >> 5;
    const int lane = tid & 31;
    const int wm   = wid & 1;
    const int wn   = wid >> 1;
    const int qid  = lane >> 2;
    const int rid  = lane & 3;

    constexpr int WN  = NT / 4;      // 32 or 16
    constexpr int NFR = WN / 8;      // 4 or 2

    const __half* A = Ag + (size_t)blockIdx.z * sA;
    const int m0 = blockIdx.y * 128;
    const int n0 = blockIdx.x * NT;

    float acc[4][NFR][4];
#pragma unroll
    for (int i = 0; i < 4; i++)
#pragma unroll
        for (int j = 0; j < NFR; j++)
#pragma unroll
            for (int t = 0; t < 4; t++) acc[i][j][t] = 0.f;

    const int nc = K >> 5;
    for (int c = 0; c < nc; c++) {
        const int k0 = c << 5;
        uint4 va[2];
#pragma unroll
        for (int i = 0; i < 2; i++) {
            int idx = tid + i * 256;
            int r = idx >> 2, seg = (idx & 3) << 3;
            va[i] = *(const uint4*)(A + (size_t)(m0 + r) * lda + k0 + seg);
        }
        if (B_F32) {
            const float* B = (const float*)Bv + (size_t)blockIdx.z * sB;
            constexpr int BI = (NT * 32) / (4 * 256);
            float4 vb[BI];
#pragma unroll
            for (int i = 0; i < BI; i++) {
                int idx = tid + i * 256;
                int r = idx >> 3, seg = (idx & 7) << 2;
                vb[i] = *(const float4*)(B + (size_t)(n0 + r) * ldb + k0 + seg);
            }
            __syncthreads();
#pragma unroll
            for (int i = 0; i < 2; i++) {
                int idx = tid + i * 256;
                int r = idx >> 2, seg = (idx & 3) << 3;
                *(uint4*)&As[r][seg] = va[i];
            }
#pragma unroll
            for (int i = 0; i < BI; i++) {
                int idx = tid + i * 256;
                int r = idx >> 3, seg = (idx & 7) << 2;
                *(__half2*)&Bs[r][seg]     = __floats2half2_rn(vb[i].x, vb[i].y);
                *(__half2*)&Bs[r][seg + 2] = __floats2half2_rn(vb[i].z, vb[i].w);
            }
        } else {
            const __half* B = (const __half*)Bv + (size_t)blockIdx.z * sB;
            constexpr int BI = (NT * 32) / (8 * 256) > 0 ? (NT * 32) / (8 * 256) : 1;
            uint4 vb[BI];
#pragma unroll
            for (int i = 0; i < BI; i++) {
                int idx = tid + i * 256;
                int r = idx >> 2, seg = (idx & 3) << 3;
                vb[i] = *(const uint4*)(B + (size_t)(n0 + r) * ldb + k0 + seg);
            }
            __syncthreads();
#pragma unroll
            for (int i = 0; i < 2; i++) {
                int idx = tid + i * 256;
                int r = idx >> 2, seg = (idx & 3) << 3;
                *(uint4*)&As[r][seg] = va[i];
            }
#pragma unroll
            for (int i = 0; i < BI; i++) {
                int idx = tid + i * 256;
                int r = idx >> 2, seg = (idx & 3) << 3;
                *(uint4*)&Bs[r][seg] = vb[i];
            }
        }
        __syncthreads();

#pragma unroll
        for (int kk = 0; kk < 32; kk += 16) {
            u32 af[4][4], bf[NFR][2];
#pragma unroll
            for (int mt = 0; mt < 4; mt++) {
                int row = wm * 64 + mt * 16 + qid;
                af[mt][0] = *(const u32*)&As[row    ][kk + rid * 2];
                af[mt][1] = *(const u32*)&As[row + 8][kk + rid * 2];
                af[mt][2] = *(const u32*)&As[row    ][kk + rid * 2 + 8];
                af[mt][3] = *(const u32*)&As[row + 8][kk + rid * 2 + 8];
            }
#pragma unroll
            for (int nt = 0; nt < NFR; nt++) {
                int col = wn * WN + nt * 8 + qid;
                bf[nt][0] = *(const u32*)&Bs[col][kk + rid * 2];
                bf[nt][1] = *(const u32*)&Bs[col][kk + rid * 2 + 8];
            }
#pragma unroll
            for (int mt = 0; mt < 4; mt++)
#pragma unroll
                for (int nt = 0; nt < NFR; nt++)
                    mma_f16(acc[mt][nt], af[mt], bf[nt]);
        }
        __syncthreads();
    }

#pragma unroll
    for (int mt = 0; mt < 4; mt++) {
        int r0 = m0 + wm * 64 + mt * 16 + qid;
        int r1 = r0 + 8;
#pragma unroll
        for (int nt = 0; nt < NFR; nt++) {
            int cb = n0 + wn * WN + nt * 8 + rid * 2;
            float v0 = acc[mt][nt][0];
            float v1 = acc[mt][nt][1];
            float v2 = acc[mt][nt][2];
            float v3 = acc[mt][nt][3];
            if (mode == 0) {
                float b0 = bias[cb], b1 = bias[cb + 1];
                *(float2*)(Cf + (size_t)r0 * ldc + cb) = make_float2(v0 + b0, v1 + b1);
                *(float2*)(Cf + (size_t)r1 * ldc + cb) = make_float2(v2 + b0, v3 + b1);
            } else {
                int z = blockIdx.z, b = z >> 4, h = z & 15;
                *(__half2*)(Ch + ((size_t)b * SS + r0) * DD + h * DK + cb) =
                    __floats2half2_rn(v0, v1);
                *(__half2*)(Ch + ((size_t)b * SS + r1) * DD + h * DK + cb) =
                    __floats2half2_rn(v2, v3);
            }
        }
    }
}

// ============================================================================
// Fused softmax + colsum partials; writes fp16 probs (fp32 colsum source).
// ============================================================================
__global__ __launch_bounds__(256)
void softmax_colsum_kernel(const float* __restrict__ scores,
                           __half* __restrict__ probsh,
                           float* __restrict__ part)
{
    __shared__ float redA[8];
    __shared__ float redB[8];
    const int rb = blockIdx.x;   // 0..31
    const int bh = blockIdx.y;
    const int tid = threadIdx.x;
    const int wid = tid >> 5, lane = tid & 31;

    float cs[8];
#pragma unroll
    for (int i = 0; i < 8; i++) cs[i] = 0.f;

    for (int r = 0; r < 64; r++) {
        const float* row = scores + ((size_t)bh * SS + rb * 64 + r) * SS + tid * 8;
        float x[8];
        *(float4*)(x)     = *(const float4*)(row);
        *(float4*)(x + 4) = *(const float4*)(row + 4);

        float m = x[0];
#pragma unroll
        for (int i = 1; i < 8; i++) m = fmaxf(m, x[i]);
#pragma unroll
        for (int o = 16; o > 0; o >>= 1)
            m = fmaxf(m, __shfl_xor_sync(0xFFFFFFFF, m, o));
        if (lane == 0) redA[wid] = m;
        __syncthreads();
        m = redA[0];
#pragma unroll
        for (int w = 1; w < 8; w++) m = fmaxf(m, redA[w]);

        float s = 0.f;
#pragma unroll
        for (int i = 0; i < 8; i++) {
            x[i] = __expf(x[i] - m);
            s += x[i];
        }
#pragma unroll
        for (int o = 16; o > 0; o >>= 1)
            s += __shfl_xor_sync(0xFFFFFFFF, s, o);
        if (lane == 0) redB[wid] = s;
        __syncthreads();
        s = redB[0];
#pragma unroll
        for (int w = 1; w < 8; w++) s += redB[w];
        float inv = 1.0f / s;

        __half2 h[4];
#pragma unroll
        for (int i = 0; i < 8; i += 2) {
            float p0 = x[i] * inv, p1 = x[i + 1] * inv;
            cs[i] += p0; cs[i + 1] += p1;
            h[i >> 1] = __floats2half2_rn(p0, p1);
        }
        *(uint4*)(probsh + ((size_t)bh * SS + rb * 64 + r) * SS + tid * 8) =
            *(uint4*)h;
        __syncthreads();
    }
#pragma unroll
    for (int i = 0; i < 8; i++)
        part[((size_t)bh * 32 + rb) * SS + tid * 8 + i] = cs[i];
}

// ============================================================================
// Fused colsum-reduce + top-k mask (bitonic sort). One block per (b,h).
// Partial sums reduced in the SAME rb-ascending order as before.
// ============================================================================
__global__ void topk_mask_kernel(const float* __restrict__ part,
                                 float* __restrict__ mask)
{
    __shared__ float s[SS];
    __shared__ float cs_sh[SS];
    const int bh = blockIdx.x;
    const int tid = threadIdx.x; // 1024

    for (int j = tid; j < SS; j += 1024) {
        float sum = 0.f;
#pragma unroll
        for (int rb = 0; rb < 32; rb++)
            sum += part[((size_t)bh * 32 + rb) * SS + j];
        s[j] = sum;
        cs_sh[j] = sum;
    }
    __syncthreads();

    for (int ksz = 2; ksz <= SS; ksz <<= 1) {
        for (int j = ksz >> 1; j > 0; j >>= 1) {
            for (int i = tid; i < SS; i += 1024) {
                int p = i ^ j;
                if (p > i) {
                    bool up = ((i & ksz) == 0);
                    float a = s[i], b = s[p];
                    if ((a > b) == up) { s[i] = b; s[p] = a; }
                }
            }
            __syncthreads();
        }
    }
    float thr = s[SS - KEEP];
    mask[bh * SS + tid]        = (cs_sh[tid]        >= thr) ? 1.f : 0.f;
    mask[bh * SS + tid + 1024] = (cs_sh[tid + 1024] >= thr) ? 1.f : 0.f;
}

// ============================================================================
// Masked transpose to fp16: vtmh[bh][d][s] = fp16(vh[bh][s][d] * mask[bh][s])
// ============================================================================
__global__ void vt_mask_kernel(const float* __restrict__ vh,
                               const float* __restrict__ mask,
                               __half* __restrict__ vtmh)
{
    __shared__ float t[32][33];
    const int bh = blockIdx.z;
    const int s0 = blockIdx.x * 32;
    const int d0 = blockIdx.y * 32;
    const int lx = threadIdx.x & 31;
    const int ly = threadIdx.x >> 5;
    for (int i = ly; i < 32; i += 8)
        t[i][lx] = vh[((size_t)bh * SS + s0 + i) * DK + d0 + lx] * mask[bh * SS + s0 + i];
    __syncthreads();
    for (int i = ly; i < 32; i += 8)
        vtmh[((size_t)bh * DK + d0 + i) * SS + s0 + lx] = __float2half_rn(t[lx][i]);
}

// ---------------------------------------------------------------------------
extern "C" void kernel_launch(void* const* d_in, const int* in_sizes, int n_in,
                              void* d_out, int out_size)
{
    (void)in_sizes; (void)n_in; (void)out_size;
    const float* q  = (const float*)d_in[0];
    const float* k  = (const float*)d_in[1];
    const float* v  = (const float*)d_in[2];
    const float* Wq = (const float*)d_in[3];
    const float* bq = (const float*)d_in[4];
    const float* Wk = (const float*)d_in[5];
    const float* bk = (const float*)d_in[6];
    const float* Wv = (const float*)d_in[7];
    const float* bv = (const float*)d_in[8];
    const float* Wo = (const float*)d_in[9];
    const float* bo = (const float*)d_in[10];
    float* out = (float*)d_out;

    float *qh, *kh, *vh, *probs, *part, *mask;
    __half *vtmh, *probsh, *concath;
    cudaGetSymbolAddress((void**)&qh,      g_qh);
    cudaGetSymbolAddress((void**)&kh,      g_kh);
    cudaGetSymbolAddress((void**)&vh,      g_vh);
    cudaGetSymbolAddress((void**)&vtmh,    g_vtmh);
    cudaGetSymbolAddress((void**)&probs,   g_probs);
    cudaGetSymbolAddress((void**)&probsh,  g_probsh);
    cudaGetSymbolAddress((void**)&part,    g_part);
    cudaGetSymbolAddress((void**)&mask,    g_mask);
    cudaGetSymbolAddress((void**)&concath, g_concath);

    // Q + K projections in one launch (fp32 FFMA, selection-exact)
    dim3 gqk(DD / 128, (BB * SS) / 128, 2);
    sgemm_qk<<<gqk, 256>>>(q, Wq, bq, qh, k, Wk, bk, kh);

    // V projection: fp16x3 split mma (22-bit, value path)
    dim3 gproj(DD / 128, (BB * SS) / 128, 1);
    hgemm3_proj<<<gproj, 256>>>(v, Wv, vh, bv);

    // Scores: fp32 FFMA, batched per (b,h), alpha = 1/8
    dim3 gsc(SS / 128, SS / 128, BHN);
    sgemm_scores<<<gsc, 256>>>(qh, kh, probs);

    // Fused softmax + colsum partials (fp16 probs out)
    softmax_colsum_kernel<<<dim3(32, BHN), 256>>>(probs, probsh, part);

    // Fused colsum reduce + top-k mask
    topk_mask_kernel<<<BHN, 1024>>>(part, mask);

    // Masked V transpose -> fp16 vtmh[bh][d][s]
    vt_mask_kernel<<<dim3(SS / 32, DK / 32, BHN), 256>>>(vh, mask, vtmh);

    // AV (fp16 mma): per (b,h) 2048x64x2048 -> fp16 concat
    dim3 gav(1, SS / 128, BHN);
    hgemm_nt<64, false><<<gav, 256>>>(probsh, vtmh, nullptr, concath, nullptr,
                                      SS, SS, SS, 0,
                                      (long long)SS * SS, (long long)DK * SS, 3);

    // Output projection (fp16 mma, Wo cvt on load): fp32 out + bias
    dim3 gop(DD / 128, (BB * SS) / 128, 1);
    hgemm_nt<128, true><<<gop, 256>>>(concath, Wo, out, nullptr, bo,
                                      DD, DD, DD, DD, 0, 0, 0);
}

// round 9
// speedup vs baseline: 1.6881x; 1.0427x over previous
#include <cuda_runtime.h>
#include <cuda_fp16.h>
#include <math.h>

// Problem constants
#define BB   2
#define HH   16
#define SS   2048
#define DD   1024
#define DK   64
#define BHN  (BB*HH)      // 32
#define KEEP 1843         // int(2048*0.9)

typedef unsigned int u32;

// ---------------- scratch (device globals; no cudaMalloc allowed) ----------
__device__ float  g_qh[(size_t)BHN * SS * DK];      // [b,h,s,d]
__device__ float  g_kh[(size_t)BHN * SS * DK];
__device__ float  g_vh[(size_t)BHN * SS * DK];
__device__ __half g_vtmh[(size_t)BHN * DK * SS];    // masked V^T fp16 [b,h,d,s]
__device__ float  g_probs[(size_t)BHN * SS * SS];   // 512 MiB fp32 scores
__device__ __half g_probsh[(size_t)BHN * SS * SS];  // 256 MiB fp16 probs
__device__ float  g_part[(size_t)BHN * 32 * SS];    // colsum partials
__device__ float  g_mask[BHN * SS];
__device__ __half g_concath[(size_t)BB * SS * DD];  // fp16 concat [b,s,h*64+d]

// ============================================================================
// FFMA fp32 NT GEMM body (selection-critical path), double-buffered smem.
// Accumulation order identical to R1..R8 => bitwise-same scores/selection.
// MODE 0: row-major C (ldc); MODE 1: head-scatter [b,h,s,d].
// ============================================================================
template<int MODE>
__device__ __forceinline__ void ffma_tile(
    const float* __restrict__ A, const float* __restrict__ B,
    float* __restrict__ C, const float* __restrict__ bias,
    int K, int lda, int ldb, int ldc, float alpha,
    float As[2][8][128], float Bs[2][8][128])
{
    const int m0 = blockIdx.y * 128;
    const int n0 = blockIdx.x * 128;
    const int tid = threadIdx.x;
    const int tx = tid & 15;
    const int ty = tid >> 4;
    const int lrow = tid >> 1;
    const int lcol = (tid & 1) * 4;

    float acc[8][8];
#pragma unroll
    for (int i = 0; i < 8; i++)
#pragma unroll
        for (int j = 0; j < 8; j++) acc[i][j] = 0.f;

    const float* Aptr = A + (size_t)(m0 + lrow) * lda + lcol;
    const float* Bptr = B + (size_t)(n0 + lrow) * ldb + lcol;

    {
        float4 av = *(const float4*)(Aptr);
        float4 bv = *(const float4*)(Bptr);
        As[0][lcol + 0][lrow] = av.x; As[0][lcol + 1][lrow] = av.y;
        As[0][lcol + 2][lrow] = av.z; As[0][lcol + 3][lrow] = av.w;
        Bs[0][lcol + 0][lrow] = bv.x; Bs[0][lcol + 1][lrow] = bv.y;
        Bs[0][lcol + 2][lrow] = bv.z; Bs[0][lcol + 3][lrow] = bv.w;
    }
    __syncthreads();

    int buf = 0;
    for (int k0 = 8; k0 < K; k0 += 8) {
        float4 av = *(const float4*)(Aptr + k0);
        float4 bv = *(const float4*)(Bptr + k0);
        const int nb = buf ^ 1;
        As[nb][lcol + 0][lrow] = av.x; As[nb][lcol + 1][lrow] = av.y;
        As[nb][lcol + 2][lrow] = av.z; As[nb][lcol + 3][lrow] = av.w;
        Bs[nb][lcol + 0][lrow] = bv.x; Bs[nb][lcol + 1][lrow] = bv.y;
        Bs[nb][lcol + 2][lrow] = bv.z; Bs[nb][lcol + 3][lrow] = bv.w;
#pragma unroll
        for (int kk = 0; kk < 8; kk++) {
            float a[8], b[8];
            *(float4*)(a)     = *(const float4*)&As[buf][kk][ty * 8];
            *(float4*)(a + 4) = *(const float4*)&As[buf][kk][ty * 8 + 4];
            *(float4*)(b)     = *(const float4*)&Bs[buf][kk][tx * 8];
            *(float4*)(b + 4) = *(const float4*)&Bs[buf][kk][tx * 8 + 4];
#pragma unroll
            for (int i = 0; i < 8; i++)
#pragma unroll
                for (int j = 0; j < 8; j++) acc[i][j] += a[i] * b[j];
        }
        __syncthreads();
        buf = nb;
    }
#pragma unroll
    for (int kk = 0; kk < 8; kk++) {
        float a[8], b[8];
        *(float4*)(a)     = *(const float4*)&As[buf][kk][ty * 8];
        *(float4*)(a + 4) = *(const float4*)&As[buf][kk][ty * 8 + 4];
        *(float4*)(b)     = *(const float4*)&Bs[buf][kk][tx * 8];
        *(float4*)(b + 4) = *(const float4*)&Bs[buf][kk][tx * 8 + 4];
#pragma unroll
        for (int i = 0; i < 8; i++)
#pragma unroll
            for (int j = 0; j < 8; j++) acc[i][j] += a[i] * b[j];
    }

    if (MODE == 0) {
#pragma unroll
        for (int i = 0; i < 8; i++) {
            int m = m0 + ty * 8 + i;
            float out[8];
#pragma unroll
            for (int j = 0; j < 8; j++) {
                int n = n0 + tx * 8 + j;
                out[j] = acc[i][j] * alpha + (bias ? bias[n] : 0.f);
            }
            float* crow = C + (size_t)m * ldc + n0 + tx * 8;
            *(float4*)(crow)     = *(float4*)(out);
            *(float4*)(crow + 4) = *(float4*)(out + 4);
        }
    } else {
#pragma unroll
        for (int i = 0; i < 8; i++) {
            int m = m0 + ty * 8 + i;
            int b = m >> 11;
            int s = m & (SS - 1);
#pragma unroll
            for (int j = 0; j < 8; j++) {
                int n = n0 + tx * 8 + j;
                int h = n >> 6;
                int d = n & 63;
                C[(((size_t)(b * HH + h)) * SS + s) * DK + d] =
                    acc[i][j] * alpha + (bias ? bias[n] : 0.f);
            }
        }
    }
}

// Q and K projections in one launch (blockIdx.z selects).
__global__ __launch_bounds__(256, 2)
void sgemm_qk(const float* __restrict__ q,  const float* __restrict__ Wq,
              const float* __restrict__ bq, float* __restrict__ qh,
              const float* __restrict__ k,  const float* __restrict__ Wk,
              const float* __restrict__ bk, float* __restrict__ kh)
{
    __shared__ float As[2][8][128];
    __shared__ float Bs[2][8][128];
    const float* A  = blockIdx.z ? k  : q;
    const float* B  = blockIdx.z ? Wk : Wq;
    const float* bi = blockIdx.z ? bk : bq;
    float*       C  = blockIdx.z ? kh : qh;
    ffma_tile<1>(A, B, C, bi, DD, DD, DD, 0, 1.f, As, Bs);
}

// ============================================================================
// fp16x3 split GEMM body (V projection): 22-bit accurate, smem via raw buffer.
// ============================================================================
static __device__ __forceinline__ void mma_f16(float* d, const u32* a, const u32* b) {
    asm volatile(
        "mma.sync.aligned.m16n8k16.row.col.f32.f16.f16.f32 "
        "{%0,%1,%2,%3}, {%4,%5,%6,%7}, {%8,%9}, {%0,%1,%2,%3};"
        : "+f"(d[0]), "+f"(d[1]), "+f"(d[2]), "+f"(d[3])
        : "r"(a[0]), "r"(a[1]), "r"(a[2]), "r"(a[3]), "r"(b[0]), "r"(b[1]));
}

__device__ void hgemm3_body(const float* __restrict__ Ag,
                            const float* __restrict__ Bg,
                            float* __restrict__ Cg,
                            const float* __restrict__ bias,
                            int m0, int n0, char* smem_raw)
{
    typedef __half (*HArr)[40];
    HArr Ah = (HArr)(smem_raw);
    HArr Al = (HArr)(smem_raw + 10240);
    HArr Bh = (HArr)(smem_raw + 20480);
    HArr Bl = (HArr)(smem_raw + 30720);

    const int tid  = threadIdx.x;
    const int wid  = tid >> 5;
    const int lane = tid & 31;
    const int wm   = wid & 1;
    const int wn   = wid >> 1;
    const int qid  = lane >> 2;
    const int rid  = lane & 3;

    float acc[4][4][4];
#pragma unroll
    for (int i = 0; i < 4; i++)
#pragma unroll
        for (int j = 0; j < 4; j++)
#pragma unroll
            for (int t = 0; t < 4; t++) acc[i][j][t] = 0.f;

    for (int c = 0; c < DD / 32; c++) {
        const int k0 = c << 5;
        float4 va[4], vb[4];
#pragma unroll
        for (int i = 0; i < 4; i++) {
            int idx = tid + i * 256;
            int r = idx >> 3, cc = (idx & 7) << 2;
            va[i] = *(const float4*)(Ag + (size_t)(m0 + r) * DD + k0 + cc);
            vb[i] = *(const float4*)(Bg + (size_t)(n0 + r) * DD + k0 + cc);
        }
        __syncthreads();
#pragma unroll
        for (int i = 0; i < 4; i++) {
            int idx = tid + i * 256;
            int r = idx >> 3, cc = (idx & 7) << 2;
            float xa[4] = {va[i].x, va[i].y, va[i].z, va[i].w};
            float xb[4] = {vb[i].x, vb[i].y, vb[i].z, vb[i].w};
#pragma unroll
            for (int t = 0; t < 4; t++) {
                __half h = __float2half_rn(xa[t]);
                Ah[r][cc + t] = h;
                Al[r][cc + t] = __float2half_rn(xa[t] - __half2float(h));
                __half g = __float2half_rn(xb[t]);
                Bh[r][cc + t] = g;
                Bl[r][cc + t] = __float2half_rn(xb[t] - __half2float(g));
            }
        }
        __syncthreads();

#pragma unroll
        for (int kk = 0; kk < 32; kk += 16) {
            u32 ah[4][4], al[4][4], bh[4][2], bl[4][2];
#pragma unroll
            for (int mt = 0; mt < 4; mt++) {
                int row = wm * 64 + mt * 16 + qid;
                ah[mt][0] = *(const u32*)&Ah[row    ][kk + rid * 2];
                ah[mt][1] = *(const u32*)&Ah[row + 8][kk + rid * 2];
                ah[mt][2] = *(const u32*)&Ah[row    ][kk + rid * 2 + 8];
                ah[mt][3] = *(const u32*)&Ah[row + 8][kk + rid * 2 + 8];
                al[mt][0] = *(const u32*)&Al[row    ][kk + rid * 2];
                al[mt][1] = *(const u32*)&Al[row + 8][kk + rid * 2];
                al[mt][2] = *(const u32*)&Al[row    ][kk + rid * 2 + 8];
                al[mt][3] = *(const u32*)&Al[row + 8][kk + rid * 2 + 8];
            }
#pragma unroll
            for (int nt = 0; nt < 4; nt++) {
                int col = wn * 32 + nt * 8 + qid;
                bh[nt][0] = *(const u32*)&Bh[col][kk + rid * 2];
                bh[nt][1] = *(const u32*)&Bh[col][kk + rid * 2 + 8];
                bl[nt][0] = *(const u32*)&Bl[col][kk + rid * 2];
                bl[nt][1] = *(const u32*)&Bl[col][kk + rid * 2 + 8];
            }
#pragma unroll
            for (int mt = 0; mt < 4; mt++)
#pragma unroll
                for (int nt = 0; nt < 4; nt++) {
                    mma_f16(acc[mt][nt], ah[mt], bh[nt]);
                    mma_f16(acc[mt][nt], ah[mt], bl[nt]);
                    mma_f16(acc[mt][nt], al[mt], bh[nt]);
                }
        }
        __syncthreads();
    }

    // head-scatter epilogue into [b,h,s,d]
#pragma unroll
    for (int mt = 0; mt < 4; mt++) {
        int r0 = m0 + wm * 64 + mt * 16 + qid;
        int r1 = r0 + 8;
#pragma unroll
        for (int nt = 0; nt < 4; nt++) {
            int cb = n0 + wn * 32 + nt * 8 + rid * 2;
            float b0 = bias[cb], b1 = bias[cb + 1];
            float v0 = acc[mt][nt][0] + b0;
            float v1 = acc[mt][nt][1] + b1;
            float v2 = acc[mt][nt][2] + b0;
            float v3 = acc[mt][nt][3] + b1;
            int h = cb >> 6, d = cb & 63;
            int b0i = r0 >> 11, s0i = r0 & (SS - 1);
            int b1i = r1 >> 11, s1i = r1 & (SS - 1);
            *(float2*)(Cg + (((size_t)(b0i * HH + h)) * SS + s0i) * DK + d) =
                make_float2(v0, v1);
            *(float2*)(Cg + (((size_t)(b1i * HH + h)) * SS + s1i) * DK + d) =
                make_float2(v2, v3);
        }
    }
}

// ============================================================================
// Fused launch: scores (FFMA, z<32) + V projection (fp16x3, z==32).
// Pipe-mixing: tensor-path CTAs hide under the FFMA wave.
// ============================================================================
__global__ __launch_bounds__(256, 2)
void sgemm_scores_vproj(const float* __restrict__ qh, const float* __restrict__ kh,
                        float* __restrict__ probs,
                        const float* __restrict__ v, const float* __restrict__ Wv,
                        const float* __restrict__ bv, float* __restrict__ vh)
{
    __shared__ __align__(16) char smem_raw[40960];

    if (blockIdx.z < 32) {
        float (*As)[8][128] = (float(*)[8][128])(smem_raw);
        float (*Bs)[8][128] = (float(*)[8][128])(smem_raw + 8192);
        const size_t z = blockIdx.z;
        ffma_tile<0>(qh + z * SS * DK, kh + z * SS * DK, probs + z * SS * SS,
                     nullptr, DK, DK, DK, SS, 0.125f, As, Bs);
    } else {
        // z == 32: 256 CTAs of V projection (32 m-tiles x 8 n-tiles)
        int flat = blockIdx.y * 16 + blockIdx.x;   // 0..255
        int m0 = (flat >> 3) * 128;
        int n0 = (flat & 7) * 128;
        hgemm3_body(v, Wv, vh, bv, m0, n0, smem_raw);
    }
}

// ============================================================================
// fp16 m16n8k16 NT GEMM (value path). A fp16, B fp16 or fp32(cvt), f32 acc.
// mode 3: AV -> fp16 concat scatter (z=(b,h)); mode 0: fp32 C + bias.
// ============================================================================
template<int NT, bool B_F32>
__global__ __launch_bounds__(256)
void hgemm_nt(const __half* __restrict__ Ag, const void* __restrict__ Bv,
              float* __restrict__ Cf, __half* __restrict__ Ch,
              const float* __restrict__ bias,
              int K, int lda, int ldb, int ldc,
              long long sA, long long sB,
              int mode)
{
    __shared__ __half As[128][56];
    __shared__ __half Bs[NT][56];

    const int tid  = threadIdx.x;
    const int wid  = tid >> 5;
    const int lane = tid & 31;
    const int wm   = wid & 1;
    const int wn   = wid >> 1;
    const int qid  = lane >> 2;
    const int rid  = lane & 3;

    constexpr int WN  = NT / 4;      // 32 or 16
    constexpr int NFR = WN / 8;      // 4 or 2

    const __half* A = Ag + (size_t)blockIdx.z * sA;
    const int m0 = blockIdx.y * 128;
    const int n0 = blockIdx.x * NT;

    float acc[4][NFR][4];
#pragma unroll
    for (int i = 0; i < 4; i++)
#pragma unroll
        for (int j = 0; j < NFR; j++)
#pragma unroll
            for (int t = 0; t < 4; t++) acc[i][j][t] = 0.f;

    const int nc = K >> 5;
    for (int c = 0; c < nc; c++) {
        const int k0 = c << 5;
        uint4 va[2];
#pragma unroll
        for (int i = 0; i < 2; i++) {
            int idx = tid + i * 256;
            int r = idx >> 2, seg = (idx & 3) << 3;
            va[i] = *(const uint4*)(A + (size_t)(m0 + r) * lda + k0 + seg);
        }
        if (B_F32) {
            const float* B = (const float*)Bv + (size_t)blockIdx.z * sB;
            constexpr int BI = (NT * 32) / (4 * 256);
            float4 vb[BI];
#pragma unroll
            for (int i = 0; i < BI; i++) {
                int idx = tid + i * 256;
                int r = idx >> 3, seg = (idx & 7) << 2;
                vb[i] = *(const float4*)(B + (size_t)(n0 + r) * ldb + k0 + seg);
            }
            __syncthreads();
#pragma unroll
            for (int i = 0; i < 2; i++) {
                int idx = tid + i * 256;
                int r = idx >> 2, seg = (idx & 3) << 3;
                *(uint4*)&As[r][seg] = va[i];
            }
#pragma unroll
            for (int i = 0; i < BI; i++) {
                int idx = tid + i * 256;
                int r = idx >> 3, seg = (idx & 7) << 2;
                *(__half2*)&Bs[r][seg]     = __floats2half2_rn(vb[i].x, vb[i].y);
                *(__half2*)&Bs[r][seg + 2] = __floats2half2_rn(vb[i].z, vb[i].w);
            }
        } else {
            const __half* B = (const __half*)Bv + (size_t)blockIdx.z * sB;
            constexpr int BI = (NT * 32) / (8 * 256) > 0 ? (NT * 32) / (8 * 256) : 1;
            uint4 vb[BI];
#pragma unroll
            for (int i = 0; i < BI; i++) {
                int idx = tid + i * 256;
                int r = idx >> 2, seg = (idx & 3) << 3;
                vb[i] = *(const uint4*)(B + (size_t)(n0 + r) * ldb + k0 + seg);
            }
            __syncthreads();
#pragma unroll
            for (int i = 0; i < 2; i++) {
                int idx = tid + i * 256;
                int r = idx >> 2, seg = (idx & 3) << 3;
                *(uint4*)&As[r][seg] = va[i];
            }
#pragma unroll
            for (int i = 0; i < BI; i++) {
                int idx = tid + i * 256;
                int r = idx >> 2, seg = (idx & 3) << 3;
                *(uint4*)&Bs[r][seg] = vb[i];
            }
        }
        __syncthreads();

#pragma unroll
        for (int kk = 0; kk < 32; kk += 16) {
            u32 af[4][4], bf[NFR][2];
#pragma unroll
            for (int mt = 0; mt < 4; mt++) {
                int row = wm * 64 + mt * 16 + qid;
                af[mt][0] = *(const u32*)&As[row    ][kk + rid * 2];
                af[mt][1] = *(const u32*)&As[row + 8][kk + rid * 2];
                af[mt][2] = *(const u32*)&As[row    ][kk + rid * 2 + 8];
                af[mt][3] = *(const u32*)&As[row + 8][kk + rid * 2 + 8];
            }
#pragma unroll
            for (int nt = 0; nt < NFR; nt++) {
                int col = wn * WN + nt * 8 + qid;
                bf[nt][0] = *(const u32*)&Bs[col][kk + rid * 2];
                bf[nt][1] = *(const u32*)&Bs[col][kk + rid * 2 + 8];
            }
#pragma unroll
            for (int mt = 0; mt < 4; mt++)
#pragma unroll
                for (int nt = 0; nt < NFR; nt++)
                    mma_f16(acc[mt][nt], af[mt], bf[nt]);
        }
        __syncthreads();
    }

#pragma unroll
    for (int mt = 0; mt < 4; mt++) {
        int r0 = m0 + wm * 64 + mt * 16 + qid;
        int r1 = r0 + 8;
#pragma unroll
        for (int nt = 0; nt < NFR; nt++) {
            int cb = n0 + wn * WN + nt * 8 + rid * 2;
            float v0 = acc[mt][nt][0];
            float v1 = acc[mt][nt][1];
            float v2 = acc[mt][nt][2];
            float v3 = acc[mt][nt][3];
            if (mode == 0) {
                float b0 = bias[cb], b1 = bias[cb + 1];
                *(float2*)(Cf + (size_t)r0 * ldc + cb) = make_float2(v0 + b0, v1 + b1);
                *(float2*)(Cf + (size_t)r1 * ldc + cb) = make_float2(v2 + b0, v3 + b1);
            } else {
                int z = blockIdx.z, b = z >> 4, h = z & 15;
                *(__half2*)(Ch + ((size_t)b * SS + r0) * DD + h * DK + cb) =
                    __floats2half2_rn(v0, v1);
                *(__half2*)(Ch + ((size_t)b * SS + r1) * DD + h * DK + cb) =
                    __floats2half2_rn(v2, v3);
            }
        }
    }
}

// ============================================================================
// Fused softmax + colsum partials; fp16 probs out. Two rows per iteration
// (ILP), per-row reduction sequence & cs order bitwise identical to R8.
// ============================================================================
__global__ __launch_bounds__(256)
void softmax_colsum_kernel(const float* __restrict__ scores,
                           __half* __restrict__ probsh,
                           float* __restrict__ part)
{
    __shared__ float redA[2][8];
    __shared__ float redB[2][8];
    const int rb = blockIdx.x;   // 0..31
    const int bh = blockIdx.y;
    const int tid = threadIdx.x;
    const int wid = tid >> 5, lane = tid & 31;

    float cs[8];
#pragma unroll
    for (int i = 0; i < 8; i++) cs[i] = 0.f;

    for (int r = 0; r < 64; r += 2) {
        const float* row0 = scores + ((size_t)bh * SS + rb * 64 + r) * SS + tid * 8;
        const float* row1 = row0 + SS;
        float x0[8], x1[8];
        *(float4*)(x0)     = *(const float4*)(row0);
        *(float4*)(x0 + 4) = *(const float4*)(row0 + 4);
        *(float4*)(x1)     = *(const float4*)(row1);
        *(float4*)(x1 + 4) = *(const float4*)(row1 + 4);

        float m0 = x0[0], m1 = x1[0];
#pragma unroll
        for (int i = 1; i < 8; i++) { m0 = fmaxf(m0, x0[i]); m1 = fmaxf(m1, x1[i]); }
#pragma unroll
        for (int o = 16; o > 0; o >>= 1) {
            m0 = fmaxf(m0, __shfl_xor_sync(0xFFFFFFFF, m0, o));
            m1 = fmaxf(m1, __shfl_xor_sync(0xFFFFFFFF, m1, o));
        }
        if (lane == 0) { redA[0][wid] = m0; redA[1][wid] = m1; }
        __syncthreads();
        m0 = redA[0][0]; m1 = redA[1][0];
#pragma unroll
        for (int w = 1; w < 8; w++) {
            m0 = fmaxf(m0, redA[0][w]);
            m1 = fmaxf(m1, redA[1][w]);
        }

        float s0 = 0.f, s1 = 0.f;
#pragma unroll
        for (int i = 0; i < 8; i++) {
            x0[i] = __expf(x0[i] - m0); s0 += x0[i];
            x1[i] = __expf(x1[i] - m1); s1 += x1[i];
        }
#pragma unroll
        for (int o = 16; o > 0; o >>= 1) {
            s0 += __shfl_xor_sync(0xFFFFFFFF, s0, o);
            s1 += __shfl_xor_sync(0xFFFFFFFF, s1, o);
        }
        if (lane == 0) { redB[0][wid] = s0; redB[1][wid] = s1; }
        __syncthreads();
        s0 = redB[0][0]; s1 = redB[1][0];
#pragma unroll
        for (int w = 1; w < 8; w++) { s0 += redB[0][w]; s1 += redB[1][w]; }
        float inv0 = 1.0f / s0;
        float inv1 = 1.0f / s1;

        __half2 h0[4], h1[4];
#pragma unroll
        for (int i = 0; i < 8; i += 2) {
            float p0 = x0[i] * inv0, p1 = x0[i + 1] * inv0;
            cs[i] += p0; cs[i + 1] += p1;
            h0[i >> 1] = __floats2half2_rn(p0, p1);
        }
#pragma unroll
        for (int i = 0; i < 8; i += 2) {
            float p0 = x1[i] * inv1, p1 = x1[i + 1] * inv1;
            cs[i] += p0; cs[i + 1] += p1;
            h1[i >> 1] = __floats2half2_rn(p0, p1);
        }
        *(uint4*)(probsh + ((size_t)bh * SS + rb * 64 + r) * SS + tid * 8) =
            *(uint4*)h0;
        *(uint4*)(probsh + ((size_t)bh * SS + rb * 64 + r + 1) * SS + tid * 8) =
            *(uint4*)h1;
        __syncthreads();
    }
#pragma unroll
    for (int i = 0; i < 8; i++)
        part[((size_t)bh * 32 + rb) * SS + tid * 8 + i] = cs[i];
}

// ============================================================================
// Fused colsum-reduce + top-k mask (bitonic sort). One block per (b,h).
// ============================================================================
__global__ void topk_mask_kernel(const float* __restrict__ part,
                                 float* __restrict__ mask)
{
    __shared__ float s[SS];
    __shared__ float cs_sh[SS];
    const int bh = blockIdx.x;
    const int tid = threadIdx.x; // 1024

    for (int j = tid; j < SS; j += 1024) {
        float sum = 0.f;
#pragma unroll
        for (int rb = 0; rb < 32; rb++)
            sum += part[((size_t)bh * 32 + rb) * SS + j];
        s[j] = sum;
        cs_sh[j] = sum;
    }
    __syncthreads();

    for (int ksz = 2; ksz <= SS; ksz <<= 1) {
        for (int j = ksz >> 1; j > 0; j >>= 1) {
            for (int i = tid; i < SS; i += 1024) {
                int p = i ^ j;
                if (p > i) {
                    bool up = ((i & ksz) == 0);
                    float a = s[i], b = s[p];
                    if ((a > b) == up) { s[i] = b; s[p] = a; }
                }
            }
            __syncthreads();
        }
    }
    float thr = s[SS - KEEP];
    mask[bh * SS + tid]        = (cs_sh[tid]        >= thr) ? 1.f : 0.f;
    mask[bh * SS + tid + 1024] = (cs_sh[tid + 1024] >= thr) ? 1.f : 0.f;
}

// ============================================================================
// Masked transpose to fp16: vtmh[bh][d][s] = fp16(vh[bh][s][d] * mask[bh][s])
// ============================================================================
__global__ void vt_mask_kernel(const float* __restrict__ vh,
                               const float* __restrict__ mask,
                               __half* __restrict__ vtmh)
{
    __shared__ float t[32][33];
    const int bh = blockIdx.z;
    const int s0 = blockIdx.x * 32;
    const int d0 = blockIdx.y * 32;
    const int lx = threadIdx.x & 31;
    const int ly = threadIdx.x >> 5;
    for (int i = ly; i < 32; i += 8)
        t[i][lx] = vh[((size_t)bh * SS + s0 + i) * DK + d0 + lx] * mask[bh * SS + s0 + i];
    __syncthreads();
    for (int i = ly; i < 32; i += 8)
        vtmh[((size_t)bh * DK + d0 + i) * SS + s0 + lx] = __float2half_rn(t[lx][i]);
}

// ---------------------------------------------------------------------------
extern "C" void kernel_launch(void* const* d_in, const int* in_sizes, int n_in,
                              void* d_out, int out_size)
{
    (void)in_sizes; (void)n_in; (void)out_size;
    const float* q  = (const float*)d_in[0];
    const float* k  = (const float*)d_in[1];
    const float* v  = (const float*)d_in[2];
    const float* Wq = (const float*)d_in[3];
    const float* bq = (const float*)d_in[4];
    const float* Wk = (const float*)d_in[5];
    const float* bk = (const float*)d_in[6];
    const float* Wv = (const float*)d_in[7];
    const float* bv = (const float*)d_in[8];
    const float* Wo = (const float*)d_in[9];
    const float* bo = (const float*)d_in[10];
    float* out = (float*)d_out;

    float *qh, *kh, *vh, *probs, *part, *mask;
    __half *vtmh, *probsh, *concath;
    cudaGetSymbolAddress((void**)&qh,      g_qh);
    cudaGetSymbolAddress((void**)&kh,      g_kh);
    cudaGetSymbolAddress((void**)&vh,      g_vh);
    cudaGetSymbolAddress((void**)&vtmh,    g_vtmh);
    cudaGetSymbolAddress((void**)&probs,   g_probs);
    cudaGetSymbolAddress((void**)&probsh,  g_probsh);
    cudaGetSymbolAddress((void**)&part,    g_part);
    cudaGetSymbolAddress((void**)&mask,    g_mask);
    cudaGetSymbolAddress((void**)&concath, g_concath);

    // Q + K projections in one launch (fp32 FFMA, selection-exact)
    dim3 gqk(DD / 128, (BB * SS) / 128, 2);
    sgemm_qk<<<gqk, 256>>>(q, Wq, bq, qh, k, Wk, bk, kh);

    // Fused: scores (FFMA, z<32) + V projection (fp16x3, z==32)
    dim3 gsv(SS / 128, SS / 128, BHN + 1);
    sgemm_scores_vproj<<<gsv, 256>>>(qh, kh, probs, v, Wv, bv, vh);

    // Fused softmax + colsum partials (fp16 probs out)
    softmax_colsum_kernel<<<dim3(32, BHN), 256>>>(probs, probsh, part);

    // Fused colsum reduce + top-k mask
    topk_mask_kernel<<<BHN, 1024>>>(part, mask);

    // Masked V transpose -> fp16 vtmh[bh][d][s]
    vt_mask_kernel<<<dim3(SS / 32, DK / 32, BHN), 256>>>(vh, mask, vtmh);

    // AV (fp16 mma): per (b,h) 2048x64x2048 -> fp16 concat
    dim3 gav(1, SS / 128, BHN);
    hgemm_nt<64, false><<<gav, 256>>>(probsh, vtmh, nullptr, concath, nullptr,
                                      SS, SS, SS, 0,
                                      (long long)SS * SS, (long long)DK * SS, 3);

    // Output projection (fp16 mma, Wo cvt on load): fp32 out + bias
    dim3 gop(DD / 128, (BB * SS) / 128, 1);
    hgemm_nt<128, true><<<gop, 256>>>(concath, Wo, out, nullptr, bo,
                                      DD, DD, DD, DD, 0, 0, 0);
}